// round 2
// baseline (speedup 1.0000x reference)
#include <cuda_runtime.h>
#include <math.h>

// Problem constants
#define B_   4
#define Q_   75
#define WAY  5
#define SHOT 5
#define HW_  100
#define D_   640
#define NK   5
#define SHW  (SHOT*HW_)   // 500

// GEMM tiling
#define BM   128
#define BNT  128
#define BK   16
#define ASTR 132          // smem stride for As/Bs (k-major, padded)
#define CSTR 129          // smem stride for C tile (conflict-free row scan)

// -------- scratch (__device__ globals; no allocation allowed) --------
__device__ __align__(16) float g_qinv [B_*Q_*HW_];        // 30000
__device__ __align__(16) float g_sinv [B_*WAY*SHOT*HW_];  // 10000
__device__ __align__(16) float g_qmean[B_*Q_*D_];         // 192000
__device__ __align__(16) float g_proto[B_*WAY*D_];        // 12800
__device__ __align__(16) float g_cos  [B_*Q_*WAY];        // 1500
__device__ __align__(16) float g_sim  [B_*Q_*WAY];        // 1500

// ---------------- reciprocal L2 norms, one warp per 640-row ----------------
__global__ void rownorm_kernel(const float* __restrict__ x, int nrows, int which) {
    int gw   = (blockIdx.x * blockDim.x + threadIdx.x) >> 5;
    int lane = threadIdx.x & 31;
    if (gw >= nrows) return;
    const float4* row = reinterpret_cast<const float4*>(x + (size_t)gw * D_);
    float s = 0.f;
#pragma unroll
    for (int i = 0; i < 5; i++) {           // 160 float4 per row, 5 per lane
        float4 v = row[lane + i * 32];
        s += v.x*v.x + v.y*v.y + v.z*v.z + v.w*v.w;
    }
#pragma unroll
    for (int o = 16; o; o >>= 1) s += __shfl_xor_sync(0xffffffffu, s, o);
    if (lane == 0) (which ? g_sinv : g_qinv)[gw] = rsqrtf(s);
}

// ---------------- query_mean[b,q,d] = mean_h qn ----------------
__global__ void qmean_kernel(const float* __restrict__ xq) {
    int bq = blockIdx.x;                    // 0..299
    __shared__ float inv_s[HW_];
    if (threadIdx.x < HW_) inv_s[threadIdx.x] = g_qinv[bq * HW_ + threadIdx.x];
    __syncthreads();
    int d = threadIdx.x;                    // 640 threads
    const float* base = xq + (size_t)bq * HW_ * D_ + d;
    float s = 0.f;
#pragma unroll 4
    for (int h = 0; h < HW_; h++) s += base[(size_t)h * D_] * inv_s[h];
    g_qmean[(size_t)bq * D_ + d] = s * (1.0f / HW_);
}

// ---------------- proto[b,w,d] = mean over shot*HW of sn ----------------
__global__ void proto_kernel(const float* __restrict__ xs) {
    int bw = blockIdx.x;                    // 0..19
    __shared__ float inv_s[SHW];
    for (int i = threadIdx.x; i < SHW; i += blockDim.x)
        inv_s[i] = g_sinv[bw * SHW + i];
    __syncthreads();
    int d = threadIdx.x;                    // 640 threads
    const float* base = xs + (size_t)bw * SHW * D_ + d;
    float s = 0.f;
#pragma unroll 4
    for (int r = 0; r < SHW; r++) s += base[(size_t)r * D_] * inv_s[r];
    g_proto[(size_t)bw * D_ + d] = s * (1.0f / SHW);
}

// ---------------- logits_cos[b,q,w] = qmean . proto ----------------
__global__ void cos_kernel() {
    int blk = blockIdx.x;                   // (b*Q+q)*WAY + w
    int w  = blk % WAY;
    int bq = blk / WAY;
    int b  = bq / Q_;
    const float4* qm = reinterpret_cast<const float4*>(g_qmean + (size_t)bq * D_);
    const float4* pr = reinterpret_cast<const float4*>(g_proto + (size_t)(b*WAY + w) * D_);
    int lane = threadIdx.x;                 // 32 threads
    float s = 0.f;
#pragma unroll
    for (int i = 0; i < 5; i++) {
        float4 a = qm[lane + i * 32];
        float4 c = pr[lane + i * 32];
        s += a.x*c.x + a.y*c.y + a.z*c.z + a.w*c.w;
    }
#pragma unroll
    for (int o = 16; o; o >>= 1) s += __shfl_xor_sync(0xffffffffu, s, o);
    if (lane == 0) g_cos[blk] = s;
}

// ---------------- fused GEMM (100x500x640) + running top-5 + mean ----------------
// block = (b, q, w); 256 threads; thread (tx,ty) in 16x16 computes 8x8 micro-tile
__global__ __launch_bounds__(256, 2)
void fused_dn4_kernel(const float* __restrict__ xq, const float* __restrict__ xs) {
    extern __shared__ float sm[];
    float* As     = sm;                         // BK*ASTR
    float* Bs     = As + BK * ASTR;             // BK*ASTR
    float* Cs     = Bs + BK * ASTR;             // 128*CSTR
    float* qinv_s = Cs + 128 * CSTR;            // 128 (100 used)
    float* sinv_s = qinv_s + 128;               // 512 (500 used)

    int blk = blockIdx.x;
    int w   = blk % WAY;
    int bq  = blk / WAY;
    int b   = bq / Q_;
    const float* A  = xq + (size_t)bq * HW_ * D_;             // [100][640]
    const float* Bp = xs + (size_t)(b*WAY + w) * SHW * D_;    // [500][640]

    int tid = threadIdx.x;
    for (int i = tid; i < HW_; i += 256) qinv_s[i] = g_qinv[bq * HW_ + i];
    for (int i = tid; i < SHW; i += 256) sinv_s[i] = g_sinv[(b*WAY + w) * SHW + i];
    __syncthreads();

    int tx = tid & 15, ty = tid >> 4;

    float t0 = -1e30f, t1 = -1e30f, t2 = -1e30f, t3 = -1e30f, t4 = -1e30f;

    for (int nt = 0; nt < 4; nt++) {
        float acc[8][8];
#pragma unroll
        for (int i = 0; i < 8; i++)
#pragma unroll
            for (int j = 0; j < 8; j++) acc[i][j] = 0.f;

        for (int kt = 0; kt < D_ / BK; kt++) {
            // ---- stage global -> regs (2 float4 for A, 2 for B per thread) ----
            float4 av[2], bv[2];
            int am[2], ak[2];
#pragma unroll
            for (int li = 0; li < 2; li++) {
                int L  = tid + li * 256;      // 0..511 (float4 units)
                int m  = L >> 2;              // row 0..127
                int kq = (L & 3) << 2;        // k sub-offset 0,4,8,12
                am[li] = m; ak[li] = kq;
                if (m < HW_) {
                    float4 v = *reinterpret_cast<const float4*>(A + (size_t)m * D_ + kt * BK + kq);
                    float sc = qinv_s[m];
                    av[li] = make_float4(v.x*sc, v.y*sc, v.z*sc, v.w*sc);
                } else av[li] = make_float4(0.f, 0.f, 0.f, 0.f);
                int ng = nt * BNT + m;
                if (ng < SHW) {
                    float4 v = *reinterpret_cast<const float4*>(Bp + (size_t)ng * D_ + kt * BK + kq);
                    float sc = sinv_s[ng];
                    bv[li] = make_float4(v.x*sc, v.y*sc, v.z*sc, v.w*sc);
                } else bv[li] = make_float4(0.f, 0.f, 0.f, 0.f);
            }
            __syncthreads();   // previous compute finished reading smem
#pragma unroll
            for (int li = 0; li < 2; li++) {
                int m = am[li], kq = ak[li];
                As[(kq+0)*ASTR + m] = av[li].x;
                As[(kq+1)*ASTR + m] = av[li].y;
                As[(kq+2)*ASTR + m] = av[li].z;
                As[(kq+3)*ASTR + m] = av[li].w;
                Bs[(kq+0)*ASTR + m] = bv[li].x;
                Bs[(kq+1)*ASTR + m] = bv[li].y;
                Bs[(kq+2)*ASTR + m] = bv[li].z;
                Bs[(kq+3)*ASTR + m] = bv[li].w;
            }
            __syncthreads();
            // ---- compute ----
#pragma unroll
            for (int k = 0; k < BK; k++) {
                float a[8], bb[8];
                *reinterpret_cast<float4*>(a)    = *reinterpret_cast<const float4*>(As + k*ASTR + ty*8);
                *reinterpret_cast<float4*>(a+4)  = *reinterpret_cast<const float4*>(As + k*ASTR + ty*8 + 4);
                *reinterpret_cast<float4*>(bb)   = *reinterpret_cast<const float4*>(Bs + k*ASTR + tx*8);
                *reinterpret_cast<float4*>(bb+4) = *reinterpret_cast<const float4*>(Bs + k*ASTR + tx*8 + 4);
#pragma unroll
                for (int i = 0; i < 8; i++)
#pragma unroll
                    for (int j = 0; j < 8; j++)
                        acc[i][j] += a[i] * bb[j];
            }
        }
        // ---- stage C tile to smem ----
        __syncthreads();
#pragma unroll
        for (int i = 0; i < 8; i++)
#pragma unroll
            for (int j = 0; j < 8; j++)
                Cs[(ty*8 + i) * CSTR + tx*8 + j] = acc[i][j];
        __syncthreads();
        // ---- merge this tile's columns into running top-5 (one thread per query row) ----
        if (tid < HW_) {
            const float* row = Cs + tid * CSTR;
            int nvalid = SHW - nt * BNT; if (nvalid > BNT) nvalid = BNT;  // 128,128,128,116
            for (int c = 0; c < nvalid; c++) {
                float v = row[c];
                if (v > t4) {
                    if (v > t3) { t4 = t3;
                        if (v > t2) { t3 = t2;
                            if (v > t1) { t2 = t1;
                                if (v > t0) { t1 = t0; t0 = v; } else t1 = v;
                            } else t2 = v;
                        } else t3 = v;
                    } else t4 = v;
                }
            }
        }
        __syncthreads();
    }
    // ---- reduce mean over k and rows ----
    if (tid < HW_) Cs[tid] = t0 + t1 + t2 + t3 + t4;
    __syncthreads();
    if (tid == 0) {
        float s = 0.f;
        for (int i = 0; i < HW_; i++) s += Cs[i];
        g_sim[blk] = s * (1.0f / (HW_ * NK));
    }
}

// ---------------- BatchNorm (batch stats over q) + dilated conv ----------------
__global__ void bnconv_kernel(const float* __restrict__ gamma,
                              const float* __restrict__ beta,
                              const float* __restrict__ convw,
                              float* __restrict__ out) {
    __shared__ float mu_s[B_*2*WAY], istd_s[B_*2*WAY];
    int t = threadIdx.x;
    if (t < B_*2*WAY) {                     // 40 (b,channel) pairs
        int b = t / (2*WAY), c = t % (2*WAY);
        const float* src = (c < WAY) ? g_cos : g_sim;
        int ch = (c < WAY) ? c : c - WAY;
        float s = 0.f, s2 = 0.f;
        for (int q = 0; q < Q_; q++) {
            float v = src[(b*Q_ + q) * WAY + ch];
            s += v; s2 += v * v;
        }
        float m   = s  * (1.0f / Q_);
        float var = s2 * (1.0f / Q_) - m * m;   // biased, as torch BN
        mu_s[t]   = m;
        istd_s[t] = rsqrtf(var + 1e-5f);
    }
    __syncthreads();
    float w0 = convw[0], w1 = convw[1];
    for (int idx = t; idx < B_*Q_*WAY; idx += blockDim.x) {
        int j   = idx % WAY;
        int bq  = idx / WAY;
        int b   = bq / Q_;
        int c0  = j;          // cos channel
        int c1  = j + WAY;    // sim channel
        float f0 = g_cos[bq * WAY + j];
        float f1 = g_sim[bq * WAY + j];
        float bn0 = (f0 - mu_s[b*2*WAY + c0]) * istd_s[b*2*WAY + c0] * gamma[c0] + beta[c0];
        float bn1 = (f1 - mu_s[b*2*WAY + c1]) * istd_s[b*2*WAY + c1] * gamma[c1] + beta[c1];
        out[idx] = w0 * bn0 + w1 * bn1;
    }
}

// ---------------- launch ----------------
extern "C" void kernel_launch(void* const* d_in, const int* in_sizes, int n_in,
                              void* d_out, int out_size) {
    const float* xq    = (const float*)d_in[0];  // [4,75,100,640]
    const float* xs    = (const float*)d_in[1];  // [4,5,5,100,640]
    const float* gamma = (const float*)d_in[2];  // [10]
    const float* beta  = (const float*)d_in[3];  // [10]
    const float* convw = (const float*)d_in[4];  // [2]
    float* out = (float*)d_out;                  // [4,75,5]

    const int smem_bytes = (2 * BK * ASTR + 128 * CSTR + 128 + 512) * (int)sizeof(float); // 85504
    cudaFuncSetAttribute(fused_dn4_kernel,
                         cudaFuncAttributeMaxDynamicSharedMemorySize, smem_bytes);

    int nq_rows = B_*Q_*HW_;        // 30000
    int ns_rows = B_*WAY*SHOT*HW_;  // 10000
    rownorm_kernel<<<(nq_rows*32 + 255)/256, 256>>>(xq, nq_rows, 0);
    rownorm_kernel<<<(ns_rows*32 + 255)/256, 256>>>(xs, ns_rows, 1);
    qmean_kernel<<<B_*Q_, D_>>>(xq);
    proto_kernel<<<B_*WAY, D_>>>(xs);
    cos_kernel<<<B_*Q_*WAY, 32>>>();
    fused_dn4_kernel<<<B_*Q_*WAY, 256, smem_bytes>>>(xq, xs);
    bnconv_kernel<<<1, 256>>>(gamma, beta, convw, out);
}

// round 4
// speedup vs baseline: 2.8099x; 2.8099x over previous
#include <cuda_runtime.h>
#include <cuda_bf16.h>
#include <stdint.h>
#include <math.h>

// ---------------- problem constants ----------------
#define B_   4
#define Q_   75
#define WAY  5
#define SHOT 5
#define HW_  100
#define D_   640
#define NK   5
#define QROWS (Q_*HW_)        // 7500
#define SROWS (WAY*SHOT*HW_)  // 2500
#define SHW  (SHOT*HW_)       // 500

// ---------------- GEMM config ----------------
#define MT      128
#define NTILE   128
#define KC      64            // bf16 per k-chunk (128 bytes/row)
#define NCHUNK  (D_/KC)       // 10
#define NTCOUNT 4             // ceil(500/128)
#define TOTCH   (NTCOUNT*NCHUNK)  // 40
#define MTILES  59            // ceil(7500/128)

// smem: 2 stages of (AH|AL|BH|BL), each region 128 rows x 128B = 16KB
#define OFF_AH  0
#define OFF_AL  16384
#define OFF_BH  32768
#define OFF_BL  49152
#define STAGE_BYTES 65536
#define C_OFF   (2*STAGE_BYTES)          // 131072
#define CSTR    129
#define SMEM_TOTAL (C_OFF + 128*CSTR*4)  // 197120

#define SMEM_SWIZZLE_128B(off) ((off) ^ (((off) >> 3) & 0x70))

// ---------------- scratch ----------------
__device__ __align__(16) __nv_bfloat16 g_qh[(size_t)B_*QROWS*D_];
__device__ __align__(16) __nv_bfloat16 g_ql[(size_t)B_*QROWS*D_];
__device__ __align__(16) __nv_bfloat16 g_sh[(size_t)B_*SROWS*D_];
__device__ __align__(16) __nv_bfloat16 g_sl[(size_t)B_*SROWS*D_];
__device__ __align__(16) float g_qinv [B_*QROWS];
__device__ __align__(16) float g_sinv [B_*SROWS];
__device__ __align__(16) float g_qmean[B_*Q_*D_];
__device__ __align__(16) float g_ppart[B_*WAY*SHOT*D_];
__device__ __align__(16) float g_cos  [B_*Q_*WAY];
__device__ __align__(16) float g_sim  [B_*Q_*WAY];
__device__ __align__(16) float g_rowsim[(size_t)B_*QROWS*WAY];

// ---------------- asm helpers (all base-sm_103-legal) ----------------
__device__ __forceinline__ uint32_t smem_u32(const void* p) {
    uint32_t a;
    asm("{ .reg .u64 t; cvta.to.shared.u64 t, %1; cvt.u32.u64 %0, t; }" : "=r"(a) : "l"(p));
    return a;
}
__device__ __forceinline__ void cp16(uint32_t dst, const void* src, bool valid) {
    asm volatile("cp.async.cg.shared.global [%0], [%1], 16, %2;"
        :: "r"(dst), "l"(src), "r"(valid ? 16 : 0));
}
#define CP_COMMIT() asm volatile("cp.async.commit_group;" ::: "memory")
#define CP_WAIT1()  asm volatile("cp.async.wait_group 1;" ::: "memory")
#define CP_WAIT0()  asm volatile("cp.async.wait_group 0;" ::: "memory")

__device__ __forceinline__ void ldsm_x4(uint32_t* r, uint32_t addr) {
    asm volatile("ldmatrix.sync.aligned.m8n8.x4.shared.b16 {%0,%1,%2,%3}, [%4];"
        : "=r"(r[0]), "=r"(r[1]), "=r"(r[2]), "=r"(r[3]) : "r"(addr));
}
__device__ __forceinline__ void ldsm_x2(uint32_t* r, uint32_t addr) {
    asm volatile("ldmatrix.sync.aligned.m8n8.x2.shared.b16 {%0,%1}, [%2];"
        : "=r"(r[0]), "=r"(r[1]) : "r"(addr));
}
__device__ __forceinline__ void mma_bf16(float* c, const uint32_t* a, const uint32_t* b) {
    asm volatile("mma.sync.aligned.m16n8k16.row.col.f32.bf16.bf16.f32 "
        "{%0,%1,%2,%3}, {%4,%5,%6,%7}, {%8,%9}, {%0,%1,%2,%3};"
        : "+f"(c[0]), "+f"(c[1]), "+f"(c[2]), "+f"(c[3])
        : "r"(a[0]), "r"(a[1]), "r"(a[2]), "r"(a[3]), "r"(b[0]), "r"(b[1]));
}

// ---------------- prep: normalize + hi/lo bf16 split + inv-norms ----------------
__global__ void prep_kernel(const float* __restrict__ xq, const float* __restrict__ xs) {
    int gw   = (blockIdx.x * blockDim.x + threadIdx.x) >> 5;
    int lane = threadIdx.x & 31;
    if (gw >= B_*QROWS + B_*SROWS) return;
    const float* src; __nv_bfloat16 *dh, *dl; float* invp;
    if (gw < B_*QROWS) {
        src = xq + (size_t)gw * D_;
        dh = g_qh + (size_t)gw * D_; dl = g_ql + (size_t)gw * D_;
        invp = &g_qinv[gw];
    } else {
        int r = gw - B_*QROWS;
        src = xs + (size_t)r * D_;
        dh = g_sh + (size_t)r * D_; dl = g_sl + (size_t)r * D_;
        invp = &g_sinv[r];
    }
    const float4* row4 = reinterpret_cast<const float4*>(src);
    float s = 0.f;
    float4 v[5];
#pragma unroll
    for (int i = 0; i < 5; i++) {
        v[i] = row4[lane + i * 32];
        s += v[i].x*v[i].x + v[i].y*v[i].y + v[i].z*v[i].z + v[i].w*v[i].w;
    }
#pragma unroll
    for (int o = 16; o; o >>= 1) s += __shfl_xor_sync(0xffffffffu, s, o);
    float inv = rsqrtf(s);
    if (lane == 0) *invp = inv;
#pragma unroll
    for (int i = 0; i < 5; i++) {
        float ax = v[i].x*inv, ay = v[i].y*inv, az = v[i].z*inv, aw = v[i].w*inv;
        __nv_bfloat162 h0 = __floats2bfloat162_rn(ax, ay);
        __nv_bfloat162 h1 = __floats2bfloat162_rn(az, aw);
        float lx = ax - __bfloat162float(h0.x);
        float ly = ay - __bfloat162float(h0.y);
        float lz = az - __bfloat162float(h1.x);
        float lw = aw - __bfloat162float(h1.y);
        __nv_bfloat162 l0 = __floats2bfloat162_rn(lx, ly);
        __nv_bfloat162 l1 = __floats2bfloat162_rn(lz, lw);
        int e = (lane + i * 32) * 4;
        *reinterpret_cast<__nv_bfloat162*>(dh + e)     = h0;
        *reinterpret_cast<__nv_bfloat162*>(dh + e + 2) = h1;
        *reinterpret_cast<__nv_bfloat162*>(dl + e)     = l0;
        *reinterpret_cast<__nv_bfloat162*>(dl + e + 2) = l1;
    }
}

// ---------------- qmean ----------------
__global__ void qmean_kernel(const float* __restrict__ xq) {
    int bq = blockIdx.x;
    int d  = blockIdx.y * 128 + threadIdx.x;
    __shared__ float inv_s[HW_];
    if (threadIdx.x < HW_) inv_s[threadIdx.x] = g_qinv[bq * HW_ + threadIdx.x];
    __syncthreads();
    const float* base = xq + (size_t)bq * HW_ * D_ + d;
    float s = 0.f;
#pragma unroll 4
    for (int h = 0; h < HW_; h++) s += base[(size_t)h * D_] * inv_s[h];
    g_qmean[(size_t)bq * D_ + d] = s * (1.0f / HW_);
}

// ---------------- proto partials ----------------
__global__ void protopart_kernel(const float* __restrict__ xs) {
    int bws = blockIdx.x;
    int d   = blockIdx.y * 128 + threadIdx.x;
    __shared__ float inv_s[HW_];
    if (threadIdx.x < HW_) inv_s[threadIdx.x] = g_sinv[bws * HW_ + threadIdx.x];
    __syncthreads();
    const float* base = xs + (size_t)bws * HW_ * D_ + d;
    float s = 0.f;
#pragma unroll 4
    for (int h = 0; h < HW_; h++) s += base[(size_t)h * D_] * inv_s[h];
    g_ppart[(size_t)bws * D_ + d] = s;
}

// ---------------- cos logits ----------------
__global__ void cos_kernel() {
    int blk = blockIdx.x;
    int w  = blk % WAY;
    int bq = blk / WAY;
    int b  = bq / Q_;
    const float4* qm = reinterpret_cast<const float4*>(g_qmean + (size_t)bq * D_);
    const float4* pp = reinterpret_cast<const float4*>(g_ppart + (size_t)(b*WAY + w) * SHOT * D_);
    int lane = threadIdx.x;
    float s = 0.f;
#pragma unroll
    for (int i = 0; i < 5; i++) {
        int idx = lane + i * 32;
        float4 a = qm[idx];
        float4 p = make_float4(0.f, 0.f, 0.f, 0.f);
#pragma unroll
        for (int sh = 0; sh < SHOT; sh++) {
            float4 c = pp[(size_t)sh * (D_/4) + idx];
            p.x += c.x; p.y += c.y; p.z += c.z; p.w += c.w;
        }
        s += a.x*p.x + a.y*p.y + a.z*p.z + a.w*p.w;
    }
#pragma unroll
    for (int o = 16; o; o >>= 1) s += __shfl_xor_sync(0xffffffffu, s, o);
    if (lane == 0) g_cos[blk] = s * (1.0f / SHW);
}

// ---------------- warp-MMA bf16 split GEMM + fused top-5 ----------------
// grid (59, WAY, B_), 256 threads, 8 warps (2 x 4), warp tile 64x32
__global__ __launch_bounds__(256, 1)
void gemm_kernel() {
    extern __shared__ char smem[];
    uint32_t sb = smem_u32(smem);
    float* Cs = reinterpret_cast<float*>(smem + C_OFF);

    int tid  = threadIdx.x;
    int lane = tid & 31;
    int wid  = tid >> 5;
    int wm   = wid >> 2;          // 0..1
    int wn   = wid & 3;           // 0..3

    int mtile = blockIdx.x;
    int w = blockIdx.y;
    int b = blockIdx.z;
    int m0 = mtile * MT;

    const __nv_bfloat16* Ahb = g_qh + (size_t)b * QROWS * D_;
    const __nv_bfloat16* Alb = g_ql + (size_t)b * QROWS * D_;
    const __nv_bfloat16* Bhb = g_sh + (size_t)(b * SROWS + w * SHW) * D_;
    const __nv_bfloat16* Blb = g_sl + (size_t)(b * SROWS + w * SHW) * D_;

    // prefetch one chunk: cc -> (nt = cc/10, kc = cc%10), stage s
    auto prefetch = [&](int cc, int s) {
        int nt = cc / NCHUNK, kc = cc % NCHUNK;
        uint32_t stg = sb + s * STAGE_BYTES;
#pragma unroll
        for (int i = 0; i < 16; i++) {
            int u = tid + i * 256;          // 0..4095
            int region = u >> 10;           // 0=AH 1=AL 2=BH 3=BL
            int idx = u & 1023;
            int row = idx >> 3, f4 = idx & 7;
            uint32_t dst = stg + region * 16384
                         + SMEM_SWIZZLE_128B((uint32_t)(row * 128 + f4 * 16));
            const __nv_bfloat16* base;
            size_t goff; bool valid;
            if (region < 2) {
                int gm = m0 + row;
                valid = gm < QROWS;
                if (!valid) gm = 0;
                base = (region == 0) ? Ahb : Alb;
                goff = (size_t)gm * D_ + kc * KC + f4 * 8;
            } else {
                int gs = nt * NTILE + row;
                valid = gs < SHW;
                if (!valid) gs = 0;
                base = (region == 2) ? Bhb : Blb;
                goff = (size_t)gs * D_ + kc * KC + f4 * 8;
            }
            cp16(dst, base + goff, valid);
        }
        CP_COMMIT();
    };

    float acc[4][4][4];
#pragma unroll
    for (int mf = 0; mf < 4; mf++)
#pragma unroll
        for (int nf = 0; nf < 4; nf++)
#pragma unroll
            for (int e = 0; e < 4; e++) acc[mf][nf][e] = 0.f;

    float t0 = -1e30f, t1 = -1e30f, t2 = -1e30f, t3 = -1e30f, t4 = -1e30f;

    prefetch(0, 0);

    for (int cc = 0; cc < TOTCH; cc++) {
        if (cc + 1 < TOTCH) { prefetch(cc + 1, (cc + 1) & 1); CP_WAIT1(); }
        else CP_WAIT0();
        __syncthreads();

        uint32_t stg = sb + (cc & 1) * STAGE_BYTES;
        int arow = lane & 15;
        int brow = lane & 7;
#pragma unroll
        for (int ks = 0; ks < 4; ks++) {
            uint32_t aH[4][4], aL[4][4], bH[4][2], bL[4][2];
            int aunit = ks * 2 + (lane >> 4);
            int bunit = ks * 2 + ((lane >> 3) & 1);
#pragma unroll
            for (int mf = 0; mf < 4; mf++) {
                int r = wm * 64 + mf * 16 + arow;
                uint32_t off = SMEM_SWIZZLE_128B((uint32_t)(r * 128 + aunit * 16));
                ldsm_x4(aH[mf], stg + OFF_AH + off);
                ldsm_x4(aL[mf], stg + OFF_AL + off);
            }
#pragma unroll
            for (int nf = 0; nf < 4; nf++) {
                int r = wn * 32 + nf * 8 + brow;
                uint32_t off = SMEM_SWIZZLE_128B((uint32_t)(r * 128 + bunit * 16));
                ldsm_x2(bH[nf], stg + OFF_BH + off);
                ldsm_x2(bL[nf], stg + OFF_BL + off);
            }
#pragma unroll
            for (int mf = 0; mf < 4; mf++)
#pragma unroll
                for (int nf = 0; nf < 4; nf++) {
                    mma_bf16(acc[mf][nf], aH[mf], bH[nf]);
                    mma_bf16(acc[mf][nf], aH[mf], bL[nf]);
                    mma_bf16(acc[mf][nf], aL[mf], bH[nf]);
                }
        }

        if ((cc % NCHUNK) == NCHUNK - 1) {
            // ---- epilogue for this N tile ----
            int nt = cc / NCHUNK;
            int g  = lane >> 2;
            int c2 = (lane & 3) * 2;
            __syncthreads();   // everyone done reading stage smem (Cs separate, but cheap safety)
#pragma unroll
            for (int mf = 0; mf < 4; mf++)
#pragma unroll
                for (int nf = 0; nf < 4; nf++) {
                    int row = wm * 64 + mf * 16 + g;
                    int col = wn * 32 + nf * 8 + c2;
                    Cs[row * CSTR + col]           = acc[mf][nf][0];
                    Cs[row * CSTR + col + 1]       = acc[mf][nf][1];
                    Cs[(row + 8) * CSTR + col]     = acc[mf][nf][2];
                    Cs[(row + 8) * CSTR + col + 1] = acc[mf][nf][3];
                    acc[mf][nf][0] = acc[mf][nf][1] = acc[mf][nf][2] = acc[mf][nf][3] = 0.f;
                }
            __syncthreads();
            if (tid < 128) {
                const float* rowp = Cs + tid * CSTR;
                int nvalid = SHW - nt * NTILE; if (nvalid > NTILE) nvalid = NTILE;
                for (int c = 0; c < nvalid; c++) {
                    float v = rowp[c];
                    if (v > t4) {
                        if (v > t3) { t4 = t3;
                            if (v > t2) { t3 = t2;
                                if (v > t1) { t2 = t1;
                                    if (v > t0) { t1 = t0; t0 = v; } else t1 = v;
                                } else t2 = v;
                            } else t3 = v;
                        } else t4 = v;
                    }
                }
            }
            __syncthreads();
        } else {
            __syncthreads();   // stage (cc&1) consumed; safe to refill at cc+2
        }
    }

    if (tid < 128) {
        int gm = m0 + tid;
        if (gm < QROWS)
            g_rowsim[((size_t)b * QROWS + gm) * WAY + w] = t0 + t1 + t2 + t3 + t4;
    }
}

// ---------------- reduce rowsim -> sim ----------------
__global__ void reduce_kernel() {
    int idx = blockIdx.x * blockDim.x + threadIdx.x;
    if (idx >= B_ * Q_ * WAY) return;
    int w  = idx % WAY;
    int bq = idx / WAY;
    int b  = bq / Q_;
    int q  = bq % Q_;
    const float* base = g_rowsim + ((size_t)b * QROWS + q * HW_) * WAY + w;
    float s = 0.f;
#pragma unroll 4
    for (int h = 0; h < HW_; h++) s += base[(size_t)h * WAY];
    g_sim[idx] = s * (1.0f / (HW_ * NK));
}

// ---------------- BN (two-pass variance) + dilated conv ----------------
__global__ void bnconv_kernel(const float* __restrict__ gamma,
                              const float* __restrict__ beta,
                              const float* __restrict__ convw,
                              float* __restrict__ out) {
    __shared__ float mu_s[B_*2*WAY], istd_s[B_*2*WAY];
    int t = threadIdx.x;
    if (t < B_*2*WAY) {
        int b = t / (2*WAY), c = t % (2*WAY);
        const float* src = (c < WAY) ? g_cos : g_sim;
        int ch = (c < WAY) ? c : c - WAY;
        float s = 0.f;
        for (int q = 0; q < Q_; q++) s += src[(b*Q_ + q) * WAY + ch];
        float m = s * (1.0f / Q_);
        float v = 0.f;
        for (int q = 0; q < Q_; q++) {
            float d = src[(b*Q_ + q) * WAY + ch] - m;
            v += d * d;
        }
        mu_s[t]   = m;
        istd_s[t] = rsqrtf(v * (1.0f / Q_) + 1e-5f);
    }
    __syncthreads();
    float w0 = convw[0], w1 = convw[1];
    for (int idx = t; idx < B_*Q_*WAY; idx += blockDim.x) {
        int j  = idx % WAY;
        int bq = idx / WAY;
        int b  = bq / Q_;
        float f0 = g_cos[bq * WAY + j];
        float f1 = g_sim[bq * WAY + j];
        float bn0 = (f0 - mu_s[b*2*WAY + j])       * istd_s[b*2*WAY + j]       * gamma[j]       + beta[j];
        float bn1 = (f1 - mu_s[b*2*WAY + j + WAY]) * istd_s[b*2*WAY + j + WAY] * gamma[j + WAY] + beta[j + WAY];
        out[idx] = w0 * bn0 + w1 * bn1;
    }
}

// ---------------- launch ----------------
extern "C" void kernel_launch(void* const* d_in, const int* in_sizes, int n_in,
                              void* d_out, int out_size) {
    const float* xq    = (const float*)d_in[0];
    const float* xs    = (const float*)d_in[1];
    const float* gamma = (const float*)d_in[2];
    const float* beta  = (const float*)d_in[3];
    const float* convw = (const float*)d_in[4];
    float* out = (float*)d_out;

    cudaFuncSetAttribute(gemm_kernel,
                         cudaFuncAttributeMaxDynamicSharedMemorySize, SMEM_TOTAL);

    int nrows = B_*QROWS + B_*SROWS;   // 40000 rows, 1 warp each
    prep_kernel<<<(nrows * 32 + 255) / 256, 256>>>(xq, xs);
    qmean_kernel<<<dim3(B_*Q_, 5), 128>>>(xq);
    protopart_kernel<<<dim3(B_*WAY*SHOT, 5), 128>>>(xs);
    cos_kernel<<<B_*Q_*WAY, 32>>>();
    gemm_kernel<<<dim3(MTILES, WAY, B_), 256, SMEM_TOTAL>>>();
    reduce_kernel<<<(B_*Q_*WAY + 255) / 256, 256>>>();
    bnconv_kernel<<<1, 256>>>(gamma, beta, convw, out);
}

// round 5
// speedup vs baseline: 4.9397x; 1.7580x over previous
#include <cuda_runtime.h>
#include <cuda_bf16.h>
#include <cuda_fp16.h>
#include <stdint.h>
#include <math.h>

// ---------------- problem constants ----------------
#define B_   4
#define Q_   75
#define WAY  5
#define SHOT 5
#define HW_  100
#define D_   640
#define NK   5
#define QROWS (Q_*HW_)        // 7500
#define SROWS (WAY*SHOT*HW_)  // 2500
#define SHW  (SHOT*HW_)       // 500

// ---------------- GEMM config ----------------
#define MT      128
#define NTILE   128
#define KC      64            // fp16 per k-chunk (128 bytes/row)
#define NCHUNK  (D_/KC)       // 10
#define NTCOUNT 4
#define TOTCH   (NTCOUNT*NCHUNK)  // 40
#define MTILES  59            // ceil(7500/128)

// smem: 2 stages of (A|B), each region 128 rows x 128B = 16KB
#define OFF_A   0
#define OFF_B   16384
#define STAGE_BYTES 32768
#define C_OFF   (2*STAGE_BYTES)          // 65536
#define CSTRH   130                      // half-elements; conflict-free row scan
#define SMEM_TOTAL (C_OFF + 128*CSTRH*2) // 98816  (x2 CTAs = 197632 <= 227KB)

#define SMEM_SWIZZLE_128B(off) ((off) ^ (((off) >> 3) & 0x70))

// ---------------- scratch ----------------
__device__ __align__(16) float  g_qn[(size_t)B_*QROWS*D_];   // 76.8MB normalized fp32
__device__ __align__(16) float  g_sn[(size_t)B_*SROWS*D_];   // 25.6MB
__device__ __align__(16) __half g_qf[(size_t)B_*QROWS*D_];   // 38.4MB fp16
__device__ __align__(16) __half g_sf[(size_t)B_*SROWS*D_];   // 12.8MB
__device__ __align__(16) float g_qinv [B_*QROWS];
__device__ __align__(16) float g_sinv [B_*SROWS];
__device__ __align__(16) float g_qmean[B_*Q_*D_];
__device__ __align__(16) float g_ppart[B_*WAY*SHOT*D_];
__device__ __align__(16) float g_cos  [B_*Q_*WAY];
__device__ __align__(16) float g_sim  [B_*Q_*WAY];
__device__ __align__(16) float g_rowsim[(size_t)B_*QROWS*WAY];
__device__ __align__(16) int   g_topidx[(size_t)B_*QROWS*WAY*NK];   // 3MB

// ---------------- asm helpers ----------------
__device__ __forceinline__ uint32_t smem_u32(const void* p) {
    uint32_t a;
    asm("{ .reg .u64 t; cvta.to.shared.u64 t, %1; cvt.u32.u64 %0, t; }" : "=r"(a) : "l"(p));
    return a;
}
__device__ __forceinline__ void cp16(uint32_t dst, const void* src, bool valid) {
    asm volatile("cp.async.cg.shared.global [%0], [%1], 16, %2;"
        :: "r"(dst), "l"(src), "r"(valid ? 16 : 0));
}
#define CP_COMMIT() asm volatile("cp.async.commit_group;" ::: "memory")
#define CP_WAIT1()  asm volatile("cp.async.wait_group 1;" ::: "memory")
#define CP_WAIT0()  asm volatile("cp.async.wait_group 0;" ::: "memory")

__device__ __forceinline__ void ldsm_x4(uint32_t* r, uint32_t addr) {
    asm volatile("ldmatrix.sync.aligned.m8n8.x4.shared.b16 {%0,%1,%2,%3}, [%4];"
        : "=r"(r[0]), "=r"(r[1]), "=r"(r[2]), "=r"(r[3]) : "r"(addr));
}
__device__ __forceinline__ void ldsm_x2(uint32_t* r, uint32_t addr) {
    asm volatile("ldmatrix.sync.aligned.m8n8.x2.shared.b16 {%0,%1}, [%2];"
        : "=r"(r[0]), "=r"(r[1]) : "r"(addr));
}
__device__ __forceinline__ void mma_fp16(float* c, const uint32_t* a, const uint32_t* b) {
    asm volatile("mma.sync.aligned.m16n8k16.row.col.f32.f16.f16.f32 "
        "{%0,%1,%2,%3}, {%4,%5,%6,%7}, {%8,%9}, {%0,%1,%2,%3};"
        : "+f"(c[0]), "+f"(c[1]), "+f"(c[2]), "+f"(c[3])
        : "r"(a[0]), "r"(a[1]), "r"(a[2]), "r"(a[3]), "r"(b[0]), "r"(b[1]));
}

// ---------------- prep: normalize -> fp32 copy + fp16 copy + inv-norms ----------------
__global__ void prep_kernel(const float* __restrict__ xq, const float* __restrict__ xs) {
    int gw   = (blockIdx.x * blockDim.x + threadIdx.x) >> 5;
    int lane = threadIdx.x & 31;
    if (gw >= B_*QROWS + B_*SROWS) return;
    const float* src; float* dn; __half* df; float* invp;
    if (gw < B_*QROWS) {
        src = xq + (size_t)gw * D_;
        dn = g_qn + (size_t)gw * D_; df = g_qf + (size_t)gw * D_;
        invp = &g_qinv[gw];
    } else {
        int r = gw - B_*QROWS;
        src = xs + (size_t)r * D_;
        dn = g_sn + (size_t)r * D_; df = g_sf + (size_t)r * D_;
        invp = &g_sinv[r];
    }
    const float4* row4 = reinterpret_cast<const float4*>(src);
    float s = 0.f;
    float4 v[5];
#pragma unroll
    for (int i = 0; i < 5; i++) {
        v[i] = row4[lane + i * 32];
        s += v[i].x*v[i].x + v[i].y*v[i].y + v[i].z*v[i].z + v[i].w*v[i].w;
    }
#pragma unroll
    for (int o = 16; o; o >>= 1) s += __shfl_xor_sync(0xffffffffu, s, o);
    float inv = rsqrtf(s);
    if (lane == 0) *invp = inv;
#pragma unroll
    for (int i = 0; i < 5; i++) {
        float4 n = make_float4(v[i].x*inv, v[i].y*inv, v[i].z*inv, v[i].w*inv);
        int e = (lane + i * 32) * 4;
        *reinterpret_cast<float4*>(dn + e) = n;
        __half2 h0 = __floats2half2_rn(n.x, n.y);
        __half2 h1 = __floats2half2_rn(n.z, n.w);
        *reinterpret_cast<__half2*>(df + e)     = h0;
        *reinterpret_cast<__half2*>(df + e + 2) = h1;
    }
}

// ---------------- qmean ----------------
__global__ void qmean_kernel(const float* __restrict__ xq) {
    int bq = blockIdx.x;
    int d  = blockIdx.y * 128 + threadIdx.x;
    __shared__ float inv_s[HW_];
    if (threadIdx.x < HW_) inv_s[threadIdx.x] = g_qinv[bq * HW_ + threadIdx.x];
    __syncthreads();
    const float* base = xq + (size_t)bq * HW_ * D_ + d;
    float s = 0.f;
#pragma unroll 4
    for (int h = 0; h < HW_; h++) s += base[(size_t)h * D_] * inv_s[h];
    g_qmean[(size_t)bq * D_ + d] = s * (1.0f / HW_);
}

// ---------------- proto partials ----------------
__global__ void protopart_kernel(const float* __restrict__ xs) {
    int bws = blockIdx.x;
    int d   = blockIdx.y * 128 + threadIdx.x;
    __shared__ float inv_s[HW_];
    if (threadIdx.x < HW_) inv_s[threadIdx.x] = g_sinv[bws * HW_ + threadIdx.x];
    __syncthreads();
    const float* base = xs + (size_t)bws * HW_ * D_ + d;
    float s = 0.f;
#pragma unroll 4
    for (int h = 0; h < HW_; h++) s += base[(size_t)h * D_] * inv_s[h];
    g_ppart[(size_t)bws * D_ + d] = s;
}

// ---------------- cos logits ----------------
__global__ void cos_kernel() {
    int blk = blockIdx.x;
    int w  = blk % WAY;
    int bq = blk / WAY;
    int b  = bq / Q_;
    const float4* qm = reinterpret_cast<const float4*>(g_qmean + (size_t)bq * D_);
    const float4* pp = reinterpret_cast<const float4*>(g_ppart + (size_t)(b*WAY + w) * SHOT * D_);
    int lane = threadIdx.x;
    float s = 0.f;
#pragma unroll
    for (int i = 0; i < 5; i++) {
        int idx = lane + i * 32;
        float4 a = qm[idx];
        float4 p = make_float4(0.f, 0.f, 0.f, 0.f);
#pragma unroll
        for (int sh = 0; sh < SHOT; sh++) {
            float4 c = pp[(size_t)sh * (D_/4) + idx];
            p.x += c.x; p.y += c.y; p.z += c.z; p.w += c.w;
        }
        s += a.x*p.x + a.y*p.y + a.z*p.z + a.w*p.w;
    }
#pragma unroll
    for (int o = 16; o; o >>= 1) s += __shfl_xor_sync(0xffffffffu, s, o);
    if (lane == 0) g_cos[blk] = s * (1.0f / SHW);
}

// ---------------- single-fp16-MMA GEMM + fused top-5 index selection ----------------
// grid (59, WAY, B_), 256 threads, 8 warps (2 x 4), warp tile 64x32, 2 CTAs/SM
__global__ __launch_bounds__(256, 2)
void gemm_kernel() {
    extern __shared__ char smem[];
    uint32_t sb = smem_u32(smem);
    __half* Cs = reinterpret_cast<__half*>(smem + C_OFF);

    int tid  = threadIdx.x;
    int lane = tid & 31;
    int wid  = tid >> 5;
    int wm   = wid >> 2;
    int wn   = wid & 3;

    int mtile = blockIdx.x;
    int w = blockIdx.y;
    int b = blockIdx.z;
    int m0 = mtile * MT;

    const __half* Ab = g_qf + (size_t)b * QROWS * D_;
    const __half* Bb = g_sf + (size_t)(b * SROWS + w * SHW) * D_;

    auto prefetch = [&](int cc, int s) {
        int nt = cc / NCHUNK, kc = cc % NCHUNK;
        uint32_t stg = sb + s * STAGE_BYTES;
#pragma unroll
        for (int i = 0; i < 8; i++) {
            int u = tid + i * 256;          // 0..2047
            int region = u >> 10;           // 0=A 1=B
            int idx = u & 1023;
            int row = idx >> 3, f4 = idx & 7;
            uint32_t dst = stg + region * 16384
                         + SMEM_SWIZZLE_128B((uint32_t)(row * 128 + f4 * 16));
            const __half* base; size_t goff; bool valid;
            if (region == 0) {
                int gm = m0 + row;
                valid = gm < QROWS; if (!valid) gm = 0;
                base = Ab; goff = (size_t)gm * D_ + kc * KC + f4 * 8;
            } else {
                int gs = nt * NTILE + row;
                valid = gs < SHW; if (!valid) gs = 0;
                base = Bb; goff = (size_t)gs * D_ + kc * KC + f4 * 8;
            }
            cp16(dst, base + goff, valid);
        }
        CP_COMMIT();
    };

    float acc[4][4][4];
#pragma unroll
    for (int mf = 0; mf < 4; mf++)
#pragma unroll
        for (int nf = 0; nf < 4; nf++)
#pragma unroll
            for (int e = 0; e < 4; e++) acc[mf][nf][e] = 0.f;

    float t0 = -1e30f, t1 = -1e30f, t2 = -1e30f, t3 = -1e30f, t4 = -1e30f;
    int   i0 = 0, i1 = 0, i2 = 0, i3 = 0, i4 = 0;

    prefetch(0, 0);

    for (int cc = 0; cc < TOTCH; cc++) {
        if (cc + 1 < TOTCH) { prefetch(cc + 1, (cc + 1) & 1); CP_WAIT1(); }
        else CP_WAIT0();
        __syncthreads();

        uint32_t stg = sb + (cc & 1) * STAGE_BYTES;
        int arow = lane & 15;
        int brow = lane & 7;
#pragma unroll
        for (int ks = 0; ks < 4; ks++) {
            uint32_t aF[4][4], bF[4][2];
            int aunit = ks * 2 + (lane >> 4);
            int bunit = ks * 2 + ((lane >> 3) & 1);
#pragma unroll
            for (int mf = 0; mf < 4; mf++) {
                int r = wm * 64 + mf * 16 + arow;
                ldsm_x4(aF[mf], stg + OFF_A + SMEM_SWIZZLE_128B((uint32_t)(r * 128 + aunit * 16)));
            }
#pragma unroll
            for (int nf = 0; nf < 4; nf++) {
                int r = wn * 32 + nf * 8 + brow;
                ldsm_x2(bF[nf], stg + OFF_B + SMEM_SWIZZLE_128B((uint32_t)(r * 128 + bunit * 16)));
            }
#pragma unroll
            for (int mf = 0; mf < 4; mf++)
#pragma unroll
                for (int nf = 0; nf < 4; nf++)
                    mma_fp16(acc[mf][nf], aF[mf], bF[nf]);
        }

        if ((cc % NCHUNK) == NCHUNK - 1) {
            int nt = cc / NCHUNK;
            int g  = lane >> 2;
            int c2 = (lane & 3) * 2;
            __syncthreads();
#pragma unroll
            for (int mf = 0; mf < 4; mf++)
#pragma unroll
                for (int nf = 0; nf < 4; nf++) {
                    int row = wm * 64 + mf * 16 + g;
                    int col = wn * 32 + nf * 8 + c2;
                    *reinterpret_cast<__half2*>(&Cs[row * CSTRH + col]) =
                        __floats2half2_rn(acc[mf][nf][0], acc[mf][nf][1]);
                    *reinterpret_cast<__half2*>(&Cs[(row + 8) * CSTRH + col]) =
                        __floats2half2_rn(acc[mf][nf][2], acc[mf][nf][3]);
                    acc[mf][nf][0] = acc[mf][nf][1] = acc[mf][nf][2] = acc[mf][nf][3] = 0.f;
                }
            __syncthreads();
            if (tid < 128) {
                const __half* rowp = Cs + tid * CSTRH;
                int nvalid = SHW - nt * NTILE; if (nvalid > NTILE) nvalid = NTILE;
                int gbase = nt * NTILE;
                for (int c = 0; c < nvalid; c++) {
                    float v = __half2float(rowp[c]);
                    if (v > t4) {
                        int gi = gbase + c;
                        if (v > t3) { t4 = t3; i4 = i3;
                            if (v > t2) { t3 = t2; i3 = i2;
                                if (v > t1) { t2 = t1; i2 = i1;
                                    if (v > t0) { t1 = t0; i1 = i0; t0 = v; i0 = gi; }
                                    else       { t1 = v; i1 = gi; }
                                } else { t2 = v; i2 = gi; }
                            } else { t3 = v; i3 = gi; }
                        } else { t4 = v; i4 = gi; }
                    }
                }
            }
            __syncthreads();
        } else {
            __syncthreads();
        }
    }

    if (tid < 128) {
        int gm = m0 + tid;
        if (gm < QROWS) {
            int* dst = g_topidx + ((size_t)(b * QROWS + gm) * WAY + w) * NK;
            dst[0] = i0; dst[1] = i1; dst[2] = i2; dst[3] = i3; dst[4] = i4;
        }
    }
}

// ---------------- exact fp32 recompute of selected dots ----------------
// one warp per (b, query-row); computes all 5 w x 5 selected dots exactly
__global__ void recompute_kernel() {
    int gw   = (blockIdx.x * blockDim.x + threadIdx.x) >> 5;   // 0..29999
    int lane = threadIdx.x & 31;
    if (gw >= B_*QROWS) return;
    int b = gw / QROWS;

    const float4* q4 = reinterpret_cast<const float4*>(g_qn + (size_t)gw * D_);
    float4 qv[5];
#pragma unroll
    for (int i = 0; i < 5; i++) qv[i] = q4[lane + i * 32];

    const float* Sb = g_sn + (size_t)b * SROWS * D_;
#pragma unroll
    for (int w = 0; w < WAY; w++) {
        const int* idx = g_topidx + ((size_t)gw * WAY + w) * NK;
        float s = 0.f;
#pragma unroll
        for (int k = 0; k < NK; k++) {
            int col = idx[k];
            const float4* s4 = reinterpret_cast<const float4*>(
                Sb + (size_t)(w * SHW + col) * D_);
#pragma unroll
            for (int i = 0; i < 5; i++) {
                float4 sv = s4[lane + i * 32];
                s += qv[i].x*sv.x + qv[i].y*sv.y + qv[i].z*sv.z + qv[i].w*sv.w;
            }
        }
#pragma unroll
        for (int o = 16; o; o >>= 1) s += __shfl_xor_sync(0xffffffffu, s, o);
        if (lane == 0) g_rowsim[(size_t)gw * WAY + w] = s;
    }
}

// ---------------- reduce rowsim -> sim ----------------
__global__ void reduce_kernel() {
    int idx = blockIdx.x * blockDim.x + threadIdx.x;
    if (idx >= B_ * Q_ * WAY) return;
    int w  = idx % WAY;
    int bq = idx / WAY;
    int b  = bq / Q_;
    int q  = bq % Q_;
    const float* base = g_rowsim + ((size_t)b * QROWS + q * HW_) * WAY + w;
    float s = 0.f;
#pragma unroll 4
    for (int h = 0; h < HW_; h++) s += base[(size_t)h * WAY];
    g_sim[idx] = s * (1.0f / (HW_ * NK));
}

// ---------------- BN (two-pass variance) + dilated conv ----------------
__global__ void bnconv_kernel(const float* __restrict__ gamma,
                              const float* __restrict__ beta,
                              const float* __restrict__ convw,
                              float* __restrict__ out) {
    __shared__ float mu_s[B_*2*WAY], istd_s[B_*2*WAY];
    int t = threadIdx.x;
    if (t < B_*2*WAY) {
        int b = t / (2*WAY), c = t % (2*WAY);
        const float* src = (c < WAY) ? g_cos : g_sim;
        int ch = (c < WAY) ? c : c - WAY;
        float s = 0.f;
        for (int q = 0; q < Q_; q++) s += src[(b*Q_ + q) * WAY + ch];
        float m = s * (1.0f / Q_);
        float v = 0.f;
        for (int q = 0; q < Q_; q++) {
            float d = src[(b*Q_ + q) * WAY + ch] - m;
            v += d * d;
        }
        mu_s[t]   = m;
        istd_s[t] = rsqrtf(v * (1.0f / Q_) + 1e-5f);
    }
    __syncthreads();
    float w0 = convw[0], w1 = convw[1];
    for (int idx = t; idx < B_*Q_*WAY; idx += blockDim.x) {
        int j  = idx % WAY;
        int bq = idx / WAY;
        int b  = bq / Q_;
        float f0 = g_cos[bq * WAY + j];
        float f1 = g_sim[bq * WAY + j];
        float bn0 = (f0 - mu_s[b*2*WAY + j])       * istd_s[b*2*WAY + j]       * gamma[j]       + beta[j];
        float bn1 = (f1 - mu_s[b*2*WAY + j + WAY]) * istd_s[b*2*WAY + j + WAY] * gamma[j + WAY] + beta[j + WAY];
        out[idx] = w0 * bn0 + w1 * bn1;
    }
}

// ---------------- launch ----------------
extern "C" void kernel_launch(void* const* d_in, const int* in_sizes, int n_in,
                              void* d_out, int out_size) {
    const float* xq    = (const float*)d_in[0];
    const float* xs    = (const float*)d_in[1];
    const float* gamma = (const float*)d_in[2];
    const float* beta  = (const float*)d_in[3];
    const float* convw = (const float*)d_in[4];
    float* out = (float*)d_out;

    cudaFuncSetAttribute(gemm_kernel,
                         cudaFuncAttributeMaxDynamicSharedMemorySize, SMEM_TOTAL);

    int nrows = B_*QROWS + B_*SROWS;   // 40000 rows, 1 warp each
    prep_kernel<<<(nrows * 32 + 255) / 256, 256>>>(xq, xs);
    qmean_kernel<<<dim3(B_*Q_, 5), 128>>>(xq);
    protopart_kernel<<<dim3(B_*WAY*SHOT, 5), 128>>>(xs);
    cos_kernel<<<B_*Q_*WAY, 32>>>();
    gemm_kernel<<<dim3(MTILES, WAY, B_), 256, SMEM_TOTAL>>>();
    recompute_kernel<<<(B_*QROWS * 32 + 255) / 256, 256>>>();
    reduce_kernel<<<(B_*Q_*WAY + 255) / 256, 256>>>();
    bnconv_kernel<<<1, 256>>>(gamma, beta, convw, out);
}

// round 6
// speedup vs baseline: 5.7555x; 1.1651x over previous
#include <cuda_runtime.h>
#include <cuda_fp16.h>
#include <stdint.h>
#include <math.h>

// ---------------- problem constants ----------------
#define B_   4
#define Q_   75
#define WAY  5
#define SHOT 5
#define HW_  100
#define D_   640
#define NK   5
#define QROWS (Q_*HW_)        // 7500
#define SROWS (WAY*SHOT*HW_)  // 2500
#define SHW  (SHOT*HW_)       // 500

// ---------------- GEMM config ----------------
#define MT      128
#define NTILE   128
#define KC      64            // fp16 per k-chunk (128 bytes/row)
#define NCHUNK  (D_/KC)       // 10
#define NTCOUNT 4
#define TOTCH   (NTCOUNT*NCHUNK)  // 40
#define MTILES  59            // ceil(7500/128)

// smem: 2 stages of (A|B), each region 128 rows x 128B = 16KB
#define OFF_A   0
#define OFF_B   16384
#define STAGE_BYTES 32768
#define C_OFF   (2*STAGE_BYTES)          // 65536
#define CSTR    129                      // fp32 elements; conflict-free row scan
#define SMEM_TOTAL (C_OFF + 64*CSTR*4)   // 98560 (x2 CTAs = 197120 <= 227KB)

#define SMEM_SWIZZLE_128B(off) ((off) ^ (((off) >> 3) & 0x70))

// ---------------- scratch ----------------
__device__ __align__(16) __half g_qf[(size_t)B_*QROWS*D_];   // 38.4MB fp16 normalized
__device__ __align__(16) __half g_sf[(size_t)B_*SROWS*D_];   // 12.8MB
__device__ __align__(16) float g_qinv [B_*QROWS];
__device__ __align__(16) float g_sinv [B_*SROWS];
__device__ __align__(16) float g_qmean[B_*Q_*D_];
__device__ __align__(16) float g_ppart[B_*WAY*SHOT*D_];
__device__ __align__(16) float g_cos  [B_*Q_*WAY];
__device__ __align__(16) float g_sim  [B_*Q_*WAY];
__device__ __align__(16) float g_rowsim[(size_t)B_*QROWS*WAY];

// ---------------- asm helpers ----------------
__device__ __forceinline__ uint32_t smem_u32(const void* p) {
    uint32_t a;
    asm("{ .reg .u64 t; cvta.to.shared.u64 t, %1; cvt.u32.u64 %0, t; }" : "=r"(a) : "l"(p));
    return a;
}
__device__ __forceinline__ void cp16(uint32_t dst, const void* src, bool valid) {
    asm volatile("cp.async.cg.shared.global [%0], [%1], 16, %2;"
        :: "r"(dst), "l"(src), "r"(valid ? 16 : 0));
}
#define CP_COMMIT() asm volatile("cp.async.commit_group;" ::: "memory")
#define CP_WAIT1()  asm volatile("cp.async.wait_group 1;" ::: "memory")
#define CP_WAIT0()  asm volatile("cp.async.wait_group 0;" ::: "memory")

__device__ __forceinline__ void ldsm_x4(uint32_t* r, uint32_t addr) {
    asm volatile("ldmatrix.sync.aligned.m8n8.x4.shared.b16 {%0,%1,%2,%3}, [%4];"
        : "=r"(r[0]), "=r"(r[1]), "=r"(r[2]), "=r"(r[3]) : "r"(addr));
}
__device__ __forceinline__ void ldsm_x2(uint32_t* r, uint32_t addr) {
    asm volatile("ldmatrix.sync.aligned.m8n8.x2.shared.b16 {%0,%1}, [%2];"
        : "=r"(r[0]), "=r"(r[1]) : "r"(addr));
}
__device__ __forceinline__ void mma_fp16(float* c, const uint32_t* a, const uint32_t* b) {
    asm volatile("mma.sync.aligned.m16n8k16.row.col.f32.f16.f16.f32 "
        "{%0,%1,%2,%3}, {%4,%5,%6,%7}, {%8,%9}, {%0,%1,%2,%3};"
        : "+f"(c[0]), "+f"(c[1]), "+f"(c[2]), "+f"(c[3])
        : "r"(a[0]), "r"(a[1]), "r"(a[2]), "r"(a[3]), "r"(b[0]), "r"(b[1]));
}

// ---------------- prep: normalize -> fp16 copy + inv-norms ----------------
__global__ void prep_kernel(const float* __restrict__ xq, const float* __restrict__ xs) {
    int gw   = (blockIdx.x * blockDim.x + threadIdx.x) >> 5;
    int lane = threadIdx.x & 31;
    if (gw >= B_*QROWS + B_*SROWS) return;
    const float* src; __half* df; float* invp;
    if (gw < B_*QROWS) {
        src = xq + (size_t)gw * D_;
        df = g_qf + (size_t)gw * D_;
        invp = &g_qinv[gw];
    } else {
        int r = gw - B_*QROWS;
        src = xs + (size_t)r * D_;
        df = g_sf + (size_t)r * D_;
        invp = &g_sinv[r];
    }
    const float4* row4 = reinterpret_cast<const float4*>(src);
    float s = 0.f;
    float4 v[5];
#pragma unroll
    for (int i = 0; i < 5; i++) {
        v[i] = row4[lane + i * 32];
        s += v[i].x*v[i].x + v[i].y*v[i].y + v[i].z*v[i].z + v[i].w*v[i].w;
    }
#pragma unroll
    for (int o = 16; o; o >>= 1) s += __shfl_xor_sync(0xffffffffu, s, o);
    float inv = rsqrtf(s);
    if (lane == 0) *invp = inv;
#pragma unroll
    for (int i = 0; i < 5; i++) {
        int e = (lane + i * 32) * 4;
        __half2 h0 = __floats2half2_rn(v[i].x*inv, v[i].y*inv);
        __half2 h1 = __floats2half2_rn(v[i].z*inv, v[i].w*inv);
        *reinterpret_cast<__half2*>(df + e)     = h0;
        *reinterpret_cast<__half2*>(df + e + 2) = h1;
    }
}

// ---------------- qmean ----------------
__global__ void qmean_kernel(const float* __restrict__ xq) {
    int bq = blockIdx.x;
    int d  = blockIdx.y * 128 + threadIdx.x;
    __shared__ float inv_s[HW_];
    if (threadIdx.x < HW_) inv_s[threadIdx.x] = g_qinv[bq * HW_ + threadIdx.x];
    __syncthreads();
    const float* base = xq + (size_t)bq * HW_ * D_ + d;
    float s = 0.f;
#pragma unroll 4
    for (int h = 0; h < HW_; h++) s += base[(size_t)h * D_] * inv_s[h];
    g_qmean[(size_t)bq * D_ + d] = s * (1.0f / HW_);
}

// ---------------- proto partials ----------------
__global__ void protopart_kernel(const float* __restrict__ xs) {
    int bws = blockIdx.x;
    int d   = blockIdx.y * 128 + threadIdx.x;
    __shared__ float inv_s[HW_];
    if (threadIdx.x < HW_) inv_s[threadIdx.x] = g_sinv[bws * HW_ + threadIdx.x];
    __syncthreads();
    const float* base = xs + (size_t)bws * HW_ * D_ + d;
    float s = 0.f;
#pragma unroll 4
    for (int h = 0; h < HW_; h++) s += base[(size_t)h * D_] * inv_s[h];
    g_ppart[(size_t)bws * D_ + d] = s;
}

// ---------------- cos logits ----------------
__global__ void cos_kernel() {
    int blk = blockIdx.x;
    int w  = blk % WAY;
    int bq = blk / WAY;
    int b  = bq / Q_;
    const float4* qm = reinterpret_cast<const float4*>(g_qmean + (size_t)bq * D_);
    const float4* pp = reinterpret_cast<const float4*>(g_ppart + (size_t)(b*WAY + w) * SHOT * D_);
    int lane = threadIdx.x;
    float s = 0.f;
#pragma unroll
    for (int i = 0; i < 5; i++) {
        int idx = lane + i * 32;
        float4 a = qm[idx];
        float4 p = make_float4(0.f, 0.f, 0.f, 0.f);
#pragma unroll
        for (int sh = 0; sh < SHOT; sh++) {
            float4 c = pp[(size_t)sh * (D_/4) + idx];
            p.x += c.x; p.y += c.y; p.z += c.z; p.w += c.w;
        }
        s += a.x*p.x + a.y*p.y + a.z*p.z + a.w*p.w;
    }
#pragma unroll
    for (int o = 16; o; o >>= 1) s += __shfl_xor_sync(0xffffffffu, s, o);
    if (lane == 0) g_cos[blk] = s * (1.0f / SHW);
}

// ---------------- fp16 MMA GEMM + fused top-5 (fp32 accumulator values) ----------------
// grid (59, WAY, B_), 256 threads, 8 warps (2 x 4), warp tile 64x32, 2 CTAs/SM
// C tile flushed in two 64-row halves so the fp32 C smem fits alongside 2 stages.
__global__ __launch_bounds__(256, 2)
void gemm_kernel() {
    extern __shared__ char smem[];
    uint32_t sb = smem_u32(smem);
    float* Cs = reinterpret_cast<float*>(smem + C_OFF);   // 64 x CSTR fp32

    int tid  = threadIdx.x;
    int lane = tid & 31;
    int wid  = tid >> 5;
    int wm   = wid >> 2;          // 0..1  (M half owned by this warp)
    int wn   = wid & 3;           // 0..3

    int mtile = blockIdx.x;
    int w = blockIdx.y;
    int b = blockIdx.z;
    int m0 = mtile * MT;

    const __half* Ab = g_qf + (size_t)b * QROWS * D_;
    const __half* Bb = g_sf + (size_t)(b * SROWS + w * SHW) * D_;

    auto prefetch = [&](int cc, int s) {
        int nt = cc / NCHUNK, kc = cc % NCHUNK;
        uint32_t stg = sb + s * STAGE_BYTES;
#pragma unroll
        for (int i = 0; i < 8; i++) {
            int u = tid + i * 256;          // 0..2047
            int region = u >> 10;           // 0=A 1=B
            int idx = u & 1023;
            int row = idx >> 3, f4 = idx & 7;
            uint32_t dst = stg + region * 16384
                         + SMEM_SWIZZLE_128B((uint32_t)(row * 128 + f4 * 16));
            const __half* base; size_t goff; bool valid;
            if (region == 0) {
                int gm = m0 + row;
                valid = gm < QROWS; if (!valid) gm = 0;
                base = Ab; goff = (size_t)gm * D_ + kc * KC + f4 * 8;
            } else {
                int gs = nt * NTILE + row;
                valid = gs < SHW; if (!valid) gs = 0;
                base = Bb; goff = (size_t)gs * D_ + kc * KC + f4 * 8;
            }
            cp16(dst, base + goff, valid);
        }
        CP_COMMIT();
    };

    float acc[4][4][4];
#pragma unroll
    for (int mf = 0; mf < 4; mf++)
#pragma unroll
        for (int nf = 0; nf < 4; nf++)
#pragma unroll
            for (int e = 0; e < 4; e++) acc[mf][nf][e] = 0.f;

    float t0 = -1e30f, t1 = -1e30f, t2 = -1e30f, t3 = -1e30f, t4 = -1e30f;

    prefetch(0, 0);

    for (int cc = 0; cc < TOTCH; cc++) {
        if (cc + 1 < TOTCH) { prefetch(cc + 1, (cc + 1) & 1); CP_WAIT1(); }
        else CP_WAIT0();
        __syncthreads();

        uint32_t stg = sb + (cc & 1) * STAGE_BYTES;
        int arow = lane & 15;
        int brow = lane & 7;
#pragma unroll
        for (int ks = 0; ks < 4; ks++) {
            uint32_t aF[4][4], bF[4][2];
            int aunit = ks * 2 + (lane >> 4);
            int bunit = ks * 2 + ((lane >> 3) & 1);
#pragma unroll
            for (int mf = 0; mf < 4; mf++) {
                int r = wm * 64 + mf * 16 + arow;
                ldsm_x4(aF[mf], stg + OFF_A + SMEM_SWIZZLE_128B((uint32_t)(r * 128 + aunit * 16)));
            }
#pragma unroll
            for (int nf = 0; nf < 4; nf++) {
                int r = wn * 32 + nf * 8 + brow;
                ldsm_x2(bF[nf], stg + OFF_B + SMEM_SWIZZLE_128B((uint32_t)(r * 128 + bunit * 16)));
            }
#pragma unroll
            for (int mf = 0; mf < 4; mf++)
#pragma unroll
                for (int nf = 0; nf < 4; nf++)
                    mma_fp16(acc[mf][nf], aF[mf], bF[nf]);
        }

        if ((cc % NCHUNK) == NCHUNK - 1) {
            // ---- epilogue for this N tile: flush fp32 C in two 64-row halves ----
            int nt = cc / NCHUNK;
            int gbase = nt * NTILE;
            int nvalid = SHW - gbase; if (nvalid > NTILE) nvalid = NTILE;
            int g  = lane >> 2;
            int c2 = (lane & 3) * 2;
#pragma unroll
            for (int half = 0; half < 2; half++) {
                __syncthreads();   // stage consumed (half 0) / previous scan done (half 1)
                if (wm == half) {
#pragma unroll
                    for (int mf = 0; mf < 4; mf++)
#pragma unroll
                        for (int nf = 0; nf < 4; nf++) {
                            int row = mf * 16 + g;           // local row in half
                            int col = wn * 32 + nf * 8 + c2;
                            Cs[row * CSTR + col]           = acc[mf][nf][0];
                            Cs[row * CSTR + col + 1]       = acc[mf][nf][1];
                            Cs[(row + 8) * CSTR + col]     = acc[mf][nf][2];
                            Cs[(row + 8) * CSTR + col + 1] = acc[mf][nf][3];
                            acc[mf][nf][0] = acc[mf][nf][1] = acc[mf][nf][2] = acc[mf][nf][3] = 0.f;
                        }
                }
                __syncthreads();
                // threads [half*64, half*64+64) scan their row (global row m0 + tid)
                int ht = tid - half * 64;
                if (ht >= 0 && ht < 64) {
                    const float* rowp = Cs + ht * CSTR;
                    for (int c = 0; c < nvalid; c++) {
                        float v = rowp[c];
                        if (v > t4) {
                            if (v > t3) { t4 = t3;
                                if (v > t2) { t3 = t2;
                                    if (v > t1) { t2 = t1;
                                        if (v > t0) { t1 = t0; t0 = v; } else t1 = v;
                                    } else t2 = v;
                                } else t3 = v;
                            } else t4 = v;
                        }
                    }
                }
            }
        } else {
            __syncthreads();   // stage (cc&1) consumed; safe to refill at cc+2
        }
    }

    if (tid < 128) {
        int gm = m0 + tid;
        if (gm < QROWS)
            g_rowsim[((size_t)(b * QROWS + gm)) * WAY + w] = t0 + t1 + t2 + t3 + t4;
    }
}

// ---------------- reduce rowsim -> sim ----------------
__global__ void reduce_kernel() {
    int idx = blockIdx.x * blockDim.x + threadIdx.x;
    if (idx >= B_ * Q_ * WAY) return;
    int w  = idx % WAY;
    int bq = idx / WAY;
    int b  = bq / Q_;
    int q  = bq % Q_;
    const float* base = g_rowsim + ((size_t)b * QROWS + q * HW_) * WAY + w;
    float s = 0.f;
#pragma unroll 4
    for (int h = 0; h < HW_; h++) s += base[(size_t)h * WAY];
    g_sim[idx] = s * (1.0f / (HW_ * NK));
}

// ---------------- BN (two-pass variance) + dilated conv ----------------
__global__ void bnconv_kernel(const float* __restrict__ gamma,
                              const float* __restrict__ beta,
                              const float* __restrict__ convw,
                              float* __restrict__ out) {
    __shared__ float mu_s[B_*2*WAY], istd_s[B_*2*WAY];
    int t = threadIdx.x;
    if (t < B_*2*WAY) {
        int b = t / (2*WAY), c = t % (2*WAY);
        const float* src = (c < WAY) ? g_cos : g_sim;
        int ch = (c < WAY) ? c : c - WAY;
        float s = 0.f;
        for (int q = 0; q < Q_; q++) s += src[(b*Q_ + q) * WAY + ch];
        float m = s * (1.0f / Q_);
        float v = 0.f;
        for (int q = 0; q < Q_; q++) {
            float d = src[(b*Q_ + q) * WAY + ch] - m;
            v += d * d;
        }
        mu_s[t]   = m;
        istd_s[t] = rsqrtf(v * (1.0f / Q_) + 1e-5f);
    }
    __syncthreads();
    float w0 = convw[0], w1 = convw[1];
    for (int idx = t; idx < B_*Q_*WAY; idx += blockDim.x) {
        int j  = idx % WAY;
        int bq = idx / WAY;
        int b  = bq / Q_;
        float f0 = g_cos[bq * WAY + j];
        float f1 = g_sim[bq * WAY + j];
        float bn0 = (f0 - mu_s[b*2*WAY + j])       * istd_s[b*2*WAY + j]       * gamma[j]       + beta[j];
        float bn1 = (f1 - mu_s[b*2*WAY + j + WAY]) * istd_s[b*2*WAY + j + WAY] * gamma[j + WAY] + beta[j + WAY];
        out[idx] = w0 * bn0 + w1 * bn1;
    }
}

// ---------------- launch ----------------
extern "C" void kernel_launch(void* const* d_in, const int* in_sizes, int n_in,
                              void* d_out, int out_size) {
    const float* xq    = (const float*)d_in[0];
    const float* xs    = (const float*)d_in[1];
    const float* gamma = (const float*)d_in[2];
    const float* beta  = (const float*)d_in[3];
    const float* convw = (const float*)d_in[4];
    float* out = (float*)d_out;

    cudaFuncSetAttribute(gemm_kernel,
                         cudaFuncAttributeMaxDynamicSharedMemorySize, SMEM_TOTAL);

    int nrows = B_*QROWS + B_*SROWS;   // 40000 rows, 1 warp each
    prep_kernel<<<(nrows * 32 + 255) / 256, 256>>>(xq, xs);
    qmean_kernel<<<dim3(B_*Q_, 5), 128>>>(xq);
    protopart_kernel<<<dim3(B_*WAY*SHOT, 5), 128>>>(xs);
    cos_kernel<<<B_*Q_*WAY, 32>>>();
    gemm_kernel<<<dim3(MTILES, WAY, B_), 256, SMEM_TOTAL>>>();
    reduce_kernel<<<(B_*Q_*WAY + 255) / 256, 256>>>();
    bnconv_kernel<<<1, 256>>>(gamma, beta, convw, out);
}

// round 7
// speedup vs baseline: 6.6416x; 1.1539x over previous
#include <cuda_runtime.h>
#include <cuda_fp16.h>
#include <stdint.h>
#include <math.h>

// ---------------- problem constants ----------------
#define B_   4
#define Q_   75
#define WAY  5
#define SHOT 5
#define HW_  100
#define D_   640
#define NK   5
#define QROWS (Q_*HW_)        // 7500
#define SROWS (WAY*SHOT*HW_)  // 2500
#define SHW  (SHOT*HW_)       // 500

// ---------------- GEMM config ----------------
#define MT      128
#define NTILE   128
#define KC      64            // fp16 per k-chunk (128 bytes/row)
#define NCHUNK  (D_/KC)       // 10
#define NTCOUNT 4
#define TOTCH   (NTCOUNT*NCHUNK)  // 40
#define MTILES  59            // ceil(7500/128)

// smem: 3 stages of (A|B), each region 128 rows x 128B = 16KB
#define OFF_A   0
#define OFF_B   16384
#define STAGE_BYTES 32768
#define NSTAGES 3
#define SMEM_TOTAL (NSTAGES*STAGE_BYTES)   // 98304 (x2 CTAs = 196608 <= 227KB)

#define SMEM_SWIZZLE_128B(off) ((off) ^ (((off) >> 3) & 0x70))

// ---------------- scratch ----------------
__device__ __align__(16) __half g_qf[(size_t)B_*QROWS*D_];   // 38.4MB fp16 normalized
__device__ __align__(16) __half g_sf[(size_t)B_*SROWS*D_];   // 12.8MB
__device__ __align__(16) float g_qmean[B_*Q_*D_];
__device__ __align__(16) float g_ppart[B_*WAY*SHOT*D_];
__device__ __align__(16) float g_cos  [B_*Q_*WAY];
__device__ __align__(16) float g_sim  [B_*Q_*WAY];
__device__ __align__(16) float g_rowsim[(size_t)B_*QROWS*WAY];

// ---------------- asm helpers ----------------
__device__ __forceinline__ uint32_t smem_u32(const void* p) {
    uint32_t a;
    asm("{ .reg .u64 t; cvta.to.shared.u64 t, %1; cvt.u32.u64 %0, t; }" : "=r"(a) : "l"(p));
    return a;
}
__device__ __forceinline__ void cp16(uint32_t dst, const void* src, bool valid) {
    asm volatile("cp.async.cg.shared.global [%0], [%1], 16, %2;"
        :: "r"(dst), "l"(src), "r"(valid ? 16 : 0));
}
#define CP_COMMIT() asm volatile("cp.async.commit_group;" ::: "memory")
#define CP_WAIT1()  asm volatile("cp.async.wait_group 1;" ::: "memory")

__device__ __forceinline__ void ldsm_x4(uint32_t* r, uint32_t addr) {
    asm volatile("ldmatrix.sync.aligned.m8n8.x4.shared.b16 {%0,%1,%2,%3}, [%4];"
        : "=r"(r[0]), "=r"(r[1]), "=r"(r[2]), "=r"(r[3]) : "r"(addr));
}
__device__ __forceinline__ void mma_fp16(float* c, const uint32_t* a, const uint32_t* b) {
    asm volatile("mma.sync.aligned.m16n8k16.row.col.f32.f16.f16.f32 "
        "{%0,%1,%2,%3}, {%4,%5,%6,%7}, {%8,%9}, {%0,%1,%2,%3};"
        : "+f"(c[0]), "+f"(c[1]), "+f"(c[2]), "+f"(c[3])
        : "r"(a[0]), "r"(a[1]), "r"(a[2]), "r"(a[3]), "r"(b[0]), "r"(b[1]));
}

__device__ __forceinline__ void top5_insert(float* t, float v) {
    if (v > t[4]) {
        if (v > t[3]) { t[4] = t[3];
            if (v > t[2]) { t[3] = t[2];
                if (v > t[1]) { t[2] = t[1];
                    if (v > t[0]) { t[1] = t[0]; t[0] = v; } else t[1] = v;
                } else t[2] = v;
            } else t[3] = v;
        } else t[4] = v;
    }
}

// ---------------- prep: normalize -> fp16 copy ----------------
__global__ void prep_kernel(const float* __restrict__ xq, const float* __restrict__ xs) {
    int gw   = (blockIdx.x * blockDim.x + threadIdx.x) >> 5;
    int lane = threadIdx.x & 31;
    if (gw >= B_*QROWS + B_*SROWS) return;
    const float* src; __half* df;
    if (gw < B_*QROWS) {
        src = xq + (size_t)gw * D_;
        df = g_qf + (size_t)gw * D_;
    } else {
        int r = gw - B_*QROWS;
        src = xs + (size_t)r * D_;
        df = g_sf + (size_t)r * D_;
    }
    const float4* row4 = reinterpret_cast<const float4*>(src);
    float s = 0.f;
    float4 v[5];
#pragma unroll
    for (int i = 0; i < 5; i++) {
        v[i] = row4[lane + i * 32];
        s += v[i].x*v[i].x + v[i].y*v[i].y + v[i].z*v[i].z + v[i].w*v[i].w;
    }
#pragma unroll
    for (int o = 16; o; o >>= 1) s += __shfl_xor_sync(0xffffffffu, s, o);
    float inv = rsqrtf(s);
#pragma unroll
    for (int i = 0; i < 5; i++) {
        int e = (lane + i * 32) * 4;
        __half2 h0 = __floats2half2_rn(v[i].x*inv, v[i].y*inv);
        __half2 h1 = __floats2half2_rn(v[i].z*inv, v[i].w*inv);
        *reinterpret_cast<__half2*>(df + e)     = h0;
        *reinterpret_cast<__half2*>(df + e + 2) = h1;
    }
}

// ---------------- qmean from fp16 normalized ----------------
__global__ void qmean_kernel() {
    int bq = blockIdx.x;
    int d  = blockIdx.y * 128 + threadIdx.x;
    const __half* base = g_qf + (size_t)bq * HW_ * D_ + d;
    float s = 0.f;
#pragma unroll 4
    for (int h = 0; h < HW_; h++) s += __half2float(base[(size_t)h * D_]);
    g_qmean[(size_t)bq * D_ + d] = s * (1.0f / HW_);
}

// ---------------- proto partials from fp16 normalized ----------------
__global__ void protopart_kernel() {
    int bws = blockIdx.x;
    int d   = blockIdx.y * 128 + threadIdx.x;
    const __half* base = g_sf + (size_t)bws * HW_ * D_ + d;
    float s = 0.f;
#pragma unroll 4
    for (int h = 0; h < HW_; h++) s += __half2float(base[(size_t)h * D_]);
    g_ppart[(size_t)bws * D_ + d] = s;
}

// ---------------- cos logits ----------------
__global__ void cos_kernel() {
    int blk = blockIdx.x;
    int w  = blk % WAY;
    int bq = blk / WAY;
    int b  = bq / Q_;
    const float4* qm = reinterpret_cast<const float4*>(g_qmean + (size_t)bq * D_);
    const float4* pp = reinterpret_cast<const float4*>(g_ppart + (size_t)(b*WAY + w) * SHOT * D_);
    int lane = threadIdx.x;
    float s = 0.f;
#pragma unroll
    for (int i = 0; i < 5; i++) {
        int idx = lane + i * 32;
        float4 a = qm[idx];
        float4 p = make_float4(0.f, 0.f, 0.f, 0.f);
#pragma unroll
        for (int sh = 0; sh < SHOT; sh++) {
            float4 c = pp[(size_t)sh * (D_/4) + idx];
            p.x += c.x; p.y += c.y; p.z += c.z; p.w += c.w;
        }
        s += a.x*p.x + a.y*p.y + a.z*p.z + a.w*p.w;
    }
#pragma unroll
    for (int o = 16; o; o >>= 1) s += __shfl_xor_sync(0xffffffffu, s, o);
    if (lane == 0) g_cos[blk] = s * (1.0f / SHW);
}

// ---------------- fp16 MMA GEMM + register-resident top-5 ----------------
// grid (59, WAY, B_), 256 threads, 8 warps as 4M x 2N, warp tile 32x64.
// Each thread owns 4 C rows; running top-5 per row in registers.
__global__ __launch_bounds__(256, 2)
void gemm_kernel() {
    extern __shared__ char smem[];
    uint32_t sb = smem_u32(smem);

    int tid  = threadIdx.x;
    int lane = tid & 31;
    int wid  = tid >> 5;
    int wm   = wid >> 1;          // 0..3 (M quarter: 32 rows)
    int wn   = wid & 1;           // 0..1 (N half: 64 cols)

    int mtile = blockIdx.x;
    int w = blockIdx.y;
    int b = blockIdx.z;
    int m0 = mtile * MT;

    const __half* Ab = g_qf + (size_t)b * QROWS * D_;
    const __half* Bb = g_sf + (size_t)(b * SROWS + w * SHW) * D_;

    auto prefetch = [&](int cc) {
        if (cc < TOTCH) {
            int nt = cc / NCHUNK, kc = cc % NCHUNK;
            uint32_t stg = sb + (cc % NSTAGES) * STAGE_BYTES;
#pragma unroll
            for (int i = 0; i < 8; i++) {
                int u = tid + i * 256;          // 0..2047
                int region = u >> 10;           // 0=A 1=B
                int idx = u & 1023;
                int row = idx >> 3, f4 = idx & 7;
                uint32_t dst = stg + region * 16384
                             + SMEM_SWIZZLE_128B((uint32_t)(row * 128 + f4 * 16));
                const __half* base; size_t goff; bool valid;
                if (region == 0) {
                    int gm = m0 + row;
                    valid = gm < QROWS; if (!valid) gm = 0;
                    base = Ab; goff = (size_t)gm * D_ + kc * KC + f4 * 8;
                } else {
                    int gs = nt * NTILE + row;
                    valid = gs < SHW; if (!valid) gs = 0;
                    base = Bb; goff = (size_t)gs * D_ + kc * KC + f4 * 8;
                }
                cp16(dst, base + goff, valid);
            }
        }
        CP_COMMIT();
    };

    float acc[2][8][4];
#pragma unroll
    for (int mf = 0; mf < 2; mf++)
#pragma unroll
        for (int nf = 0; nf < 8; nf++)
#pragma unroll
            for (int e = 0; e < 4; e++) acc[mf][nf][e] = 0.f;

    float t5[4][5];
#pragma unroll
    for (int r = 0; r < 4; r++)
#pragma unroll
        for (int k = 0; k < 5; k++) t5[r][k] = -1e30f;

    prefetch(0);
    prefetch(1);

    for (int cc = 0; cc < TOTCH; cc++) {
        CP_WAIT1();            // own group cc complete
        __syncthreads();       // all groups-cc visible; all warps done with cc-1
        prefetch(cc + 2);      // stage (cc+2)%3 == (cc-1)%3, now free

        uint32_t stg = sb + (cc % NSTAGES) * STAGE_BYTES;
        int arow = lane & 15;
        int bro  = lane & 7;
#pragma unroll
        for (int ks = 0; ks < 4; ks++) {
            uint32_t aF[2][4], bF[4][4];
            int aunit = ks * 2 + (lane >> 4);
            int bunit = ks * 2 + ((lane >> 3) & 1);
            int nsel  = (lane >> 4);   // 0 for lanes<16, 1 for lanes>=16
#pragma unroll
            for (int mf = 0; mf < 2; mf++) {
                int r = wm * 32 + mf * 16 + arow;
                ldsm_x4(aF[mf], stg + OFF_A + SMEM_SWIZZLE_128B((uint32_t)(r * 128 + aunit * 16)));
            }
#pragma unroll
            for (int nfp = 0; nfp < 4; nfp++) {
                int r = wn * 64 + (nfp * 2 + nsel) * 8 + bro;
                ldsm_x4(bF[nfp], stg + OFF_B + SMEM_SWIZZLE_128B((uint32_t)(r * 128 + bunit * 16)));
            }
#pragma unroll
            for (int mf = 0; mf < 2; mf++)
#pragma unroll
                for (int nfp = 0; nfp < 4; nfp++) {
                    mma_fp16(acc[mf][nfp*2],     aF[mf], &bF[nfp][0]);
                    mma_fp16(acc[mf][nfp*2 + 1], aF[mf], &bF[nfp][2]);
                }
        }

        if ((cc % NCHUNK) == NCHUNK - 1) {
            // ---- fold this N tile's values into per-thread running top-5 ----
            int nt = cc / NCHUNK;
            bool lastnt = (nt == NTCOUNT - 1);
            int c2 = (lane & 3) * 2;
#pragma unroll
            for (int mf = 0; mf < 2; mf++)
#pragma unroll
                for (int e = 0; e < 2; e++) {
                    int tr = mf * 2 + e;
#pragma unroll
                    for (int nf = 0; nf < 8; nf++)
#pragma unroll
                        for (int j = 0; j < 2; j++) {
                            bool ok = true;
                            if (lastnt && wn == 1) {
                                int col = 384 + 64 + nf * 8 + c2 + j;
                                ok = col < SHW;
                            }
                            if (ok) top5_insert(t5[tr], acc[mf][nf][e*2 + j]);
                            acc[mf][nf][e*2 + j] = 0.f;
                        }
                }
        }
    }

    // ---- final merge: 8 holders x 5 candidates per row, via stage smem ----
    __syncthreads();                              // stages no longer needed
    float* cand = reinterpret_cast<float*>(smem); // [128][8][5] = 20KB
    int holder = wn * 4 + (lane & 3);
#pragma unroll
    for (int mf = 0; mf < 2; mf++)
#pragma unroll
        for (int e = 0; e < 2; e++) {
            int row = wm * 32 + mf * 16 + (lane >> 2) + e * 8;
#pragma unroll
            for (int k = 0; k < 5; k++)
                cand[(row * 8 + holder) * 5 + k] = t5[mf*2 + e][k];
        }
    __syncthreads();
    if (tid < 128) {
        const float* c = cand + tid * 40;
        float f[5];
#pragma unroll
        for (int k = 0; k < 5; k++) f[k] = -1e30f;
        for (int i = 0; i < 40; i++) top5_insert(f, c[i]);
        int gm = m0 + tid;
        if (gm < QROWS)
            g_rowsim[((size_t)(b * QROWS + gm)) * WAY + w] = f[0]+f[1]+f[2]+f[3]+f[4];
    }
}

// ---------------- reduce rowsim -> sim ----------------
__global__ void reduce_kernel() {
    int idx = blockIdx.x * blockDim.x + threadIdx.x;
    if (idx >= B_ * Q_ * WAY) return;
    int w  = idx % WAY;
    int bq = idx / WAY;
    int b  = bq / Q_;
    int q  = bq % Q_;
    const float* base = g_rowsim + ((size_t)b * QROWS + q * HW_) * WAY + w;
    float s = 0.f;
#pragma unroll 4
    for (int h = 0; h < HW_; h++) s += base[(size_t)h * WAY];
    g_sim[idx] = s * (1.0f / (HW_ * NK));
}

// ---------------- BN (two-pass variance) + dilated conv ----------------
__global__ void bnconv_kernel(const float* __restrict__ gamma,
                              const float* __restrict__ beta,
                              const float* __restrict__ convw,
                              float* __restrict__ out) {
    __shared__ float mu_s[B_*2*WAY], istd_s[B_*2*WAY];
    int t = threadIdx.x;
    if (t < B_*2*WAY) {
        int b = t / (2*WAY), c = t % (2*WAY);
        const float* src = (c < WAY) ? g_cos : g_sim;
        int ch = (c < WAY) ? c : c - WAY;
        float s = 0.f;
        for (int q = 0; q < Q_; q++) s += src[(b*Q_ + q) * WAY + ch];
        float m = s * (1.0f / Q_);
        float v = 0.f;
        for (int q = 0; q < Q_; q++) {
            float d = src[(b*Q_ + q) * WAY + ch] - m;
            v += d * d;
        }
        mu_s[t]   = m;
        istd_s[t] = rsqrtf(v * (1.0f / Q_) + 1e-5f);
    }
    __syncthreads();
    float w0 = convw[0], w1 = convw[1];
    for (int idx = t; idx < B_*Q_*WAY; idx += blockDim.x) {
        int j  = idx % WAY;
        int bq = idx / WAY;
        int b  = bq / Q_;
        float f0 = g_cos[bq * WAY + j];
        float f1 = g_sim[bq * WAY + j];
        float bn0 = (f0 - mu_s[b*2*WAY + j])       * istd_s[b*2*WAY + j]       * gamma[j]       + beta[j];
        float bn1 = (f1 - mu_s[b*2*WAY + j + WAY]) * istd_s[b*2*WAY + j + WAY] * gamma[j + WAY] + beta[j + WAY];
        out[idx] = w0 * bn0 + w1 * bn1;
    }
}

// ---------------- launch ----------------
extern "C" void kernel_launch(void* const* d_in, const int* in_sizes, int n_in,
                              void* d_out, int out_size) {
    const float* xq    = (const float*)d_in[0];
    const float* xs    = (const float*)d_in[1];
    const float* gamma = (const float*)d_in[2];
    const float* beta  = (const float*)d_in[3];
    const float* convw = (const float*)d_in[4];
    float* out = (float*)d_out;

    cudaFuncSetAttribute(gemm_kernel,
                         cudaFuncAttributeMaxDynamicSharedMemorySize, SMEM_TOTAL);

    int nrows = B_*QROWS + B_*SROWS;   // 40000 rows, 1 warp each
    prep_kernel<<<(nrows * 32 + 255) / 256, 256>>>(xq, xs);
    qmean_kernel<<<dim3(B_*Q_, 5), 128>>>();
    protopart_kernel<<<dim3(B_*WAY*SHOT, 5), 128>>>();
    gemm_kernel<<<dim3(MTILES, WAY, B_), 256, SMEM_TOTAL>>>();   // launch #4 -> ncu slot
    cos_kernel<<<B_*Q_*WAY, 32>>>();
    reduce_kernel<<<(B_*Q_*WAY + 255) / 256, 256>>>();
    bnconv_kernel<<<1, 256>>>(gamma, beta, convw, out);
}

// round 8
// speedup vs baseline: 6.9084x; 1.0402x over previous
#include <cuda_runtime.h>
#include <cuda_fp16.h>
#include <stdint.h>
#include <math.h>

// ---------------- problem constants ----------------
#define B_   4
#define Q_   75
#define WAY  5
#define SHOT 5
#define HW_  100
#define D_   640
#define NK   5
#define QROWS (Q_*HW_)        // 7500
#define SROWS (WAY*SHOT*HW_)  // 2500
#define SHW  (SHOT*HW_)       // 500

// ---------------- GEMM config ----------------
#define MT      128
#define NTILE   128
#define KC      64            // fp16 per k-chunk (128 bytes/row)
#define NCHUNK  (D_/KC)       // 10
#define NTCOUNT 4
#define TOTCH   (NTCOUNT*NCHUNK)  // 40
#define MTILES  59            // ceil(7500/128)

// smem: 3 stages of (A|B), padded-linear rows of 144 bytes (conflict-free ldmatrix)
#define RSTR    144
#define OFF_A   0
#define OFF_B   (128*RSTR)              // 18432
#define STAGE_BYTES (2*128*RSTR)        // 36864
#define NSTAGES 3
#define SMEM_TOTAL (NSTAGES*STAGE_BYTES)   // 110592 (x2 CTAs = 221184)

// ---------------- scratch ----------------
__device__ __align__(16) __half g_qf[(size_t)B_*QROWS*D_];   // fp16 normalized
__device__ __align__(16) __half g_sf[(size_t)B_*SROWS*D_];
__device__ __align__(16) float g_qmean[B_*Q_*D_];
__device__ __align__(16) float g_ppart[B_*WAY*SHOT*D_];
__device__ __align__(16) float g_cos  [B_*Q_*WAY];
__device__ __align__(16) float g_sim  [B_*Q_*WAY];
__device__ __align__(16) float g_rowsim[(size_t)B_*QROWS*WAY];

// ---------------- asm helpers ----------------
__device__ __forceinline__ uint32_t smem_u32(const void* p) {
    uint32_t a;
    asm("{ .reg .u64 t; cvta.to.shared.u64 t, %1; cvt.u32.u64 %0, t; }" : "=r"(a) : "l"(p));
    return a;
}
__device__ __forceinline__ void cp16(uint32_t dst, const void* src, bool valid) {
    asm volatile("cp.async.cg.shared.global [%0], [%1], 16, %2;"
        :: "r"(dst), "l"(src), "r"(valid ? 16 : 0));
}
#define CP_COMMIT() asm volatile("cp.async.commit_group;" ::: "memory")
#define CP_WAIT1()  asm volatile("cp.async.wait_group 1;" ::: "memory")

__device__ __forceinline__ void ldsm_x4(uint32_t* r, uint32_t addr) {
    asm volatile("ldmatrix.sync.aligned.m8n8.x4.shared.b16 {%0,%1,%2,%3}, [%4];"
        : "=r"(r[0]), "=r"(r[1]), "=r"(r[2]), "=r"(r[3]) : "r"(addr));
}
__device__ __forceinline__ void mma_fp16(float* c, const uint32_t* a, const uint32_t* b) {
    asm volatile("mma.sync.aligned.m16n8k16.row.col.f32.f16.f16.f32 "
        "{%0,%1,%2,%3}, {%4,%5,%6,%7}, {%8,%9}, {%0,%1,%2,%3};"
        : "+f"(c[0]), "+f"(c[1]), "+f"(c[2]), "+f"(c[3])
        : "r"(a[0]), "r"(a[1]), "r"(a[2]), "r"(a[3]), "r"(b[0]), "r"(b[1]));
}

__device__ __forceinline__ void top5_insert(float* t, float v) {
    if (v > t[4]) {
        if (v > t[3]) { t[4] = t[3];
            if (v > t[2]) { t[3] = t[2];
                if (v > t[1]) { t[2] = t[1];
                    if (v > t[0]) { t[1] = t[0]; t[0] = v; } else t[1] = v;
                } else t[2] = v;
            } else t[3] = v;
        } else t[4] = v;
    }
}

// ---------------- prep: normalize -> fp16 copy ----------------
__global__ void prep_kernel(const float* __restrict__ xq, const float* __restrict__ xs) {
    int gw   = (blockIdx.x * blockDim.x + threadIdx.x) >> 5;
    int lane = threadIdx.x & 31;
    if (gw >= B_*QROWS + B_*SROWS) return;
    const float* src; __half* df;
    if (gw < B_*QROWS) {
        src = xq + (size_t)gw * D_;
        df = g_qf + (size_t)gw * D_;
    } else {
        int r = gw - B_*QROWS;
        src = xs + (size_t)r * D_;
        df = g_sf + (size_t)r * D_;
    }
    const float4* row4 = reinterpret_cast<const float4*>(src);
    float s = 0.f;
    float4 v[5];
#pragma unroll
    for (int i = 0; i < 5; i++) {
        v[i] = row4[lane + i * 32];
        s += v[i].x*v[i].x + v[i].y*v[i].y + v[i].z*v[i].z + v[i].w*v[i].w;
    }
#pragma unroll
    for (int o = 16; o; o >>= 1) s += __shfl_xor_sync(0xffffffffu, s, o);
    float inv = rsqrtf(s);
#pragma unroll
    for (int i = 0; i < 5; i++) {
        int e = (lane + i * 32) * 4;
        __half2 h0 = __floats2half2_rn(v[i].x*inv, v[i].y*inv);
        __half2 h1 = __floats2half2_rn(v[i].z*inv, v[i].w*inv);
        *reinterpret_cast<__half2*>(df + e)     = h0;
        *reinterpret_cast<__half2*>(df + e + 2) = h1;
    }
}

// ---------------- qmean from fp16 normalized ----------------
__global__ void qmean_kernel() {
    int bq = blockIdx.x;
    int d  = blockIdx.y * 128 + threadIdx.x;
    const __half* base = g_qf + (size_t)bq * HW_ * D_ + d;
    float s = 0.f;
#pragma unroll 4
    for (int h = 0; h < HW_; h++) s += __half2float(base[(size_t)h * D_]);
    g_qmean[(size_t)bq * D_ + d] = s * (1.0f / HW_);
}

// ---------------- proto partials from fp16 normalized ----------------
__global__ void protopart_kernel() {
    int bws = blockIdx.x;
    int d   = blockIdx.y * 128 + threadIdx.x;
    const __half* base = g_sf + (size_t)bws * HW_ * D_ + d;
    float s = 0.f;
#pragma unroll 4
    for (int h = 0; h < HW_; h++) s += __half2float(base[(size_t)h * D_]);
    g_ppart[(size_t)bws * D_ + d] = s;
}

// ---------------- cos logits ----------------
__global__ void cos_kernel() {
    int blk = blockIdx.x;
    int w  = blk % WAY;
    int bq = blk / WAY;
    int b  = bq / Q_;
    const float4* qm = reinterpret_cast<const float4*>(g_qmean + (size_t)bq * D_);
    const float4* pp = reinterpret_cast<const float4*>(g_ppart + (size_t)(b*WAY + w) * SHOT * D_);
    int lane = threadIdx.x;
    float s = 0.f;
#pragma unroll
    for (int i = 0; i < 5; i++) {
        int idx = lane + i * 32;
        float4 a = qm[idx];
        float4 p = make_float4(0.f, 0.f, 0.f, 0.f);
#pragma unroll
        for (int sh = 0; sh < SHOT; sh++) {
            float4 c = pp[(size_t)sh * (D_/4) + idx];
            p.x += c.x; p.y += c.y; p.z += c.z; p.w += c.w;
        }
        s += a.x*p.x + a.y*p.y + a.z*p.z + a.w*p.w;
    }
#pragma unroll
    for (int o = 16; o; o >>= 1) s += __shfl_xor_sync(0xffffffffu, s, o);
    if (lane == 0) g_cos[blk] = s * (1.0f / SHW);
}

// ---------------- fp16 MMA GEMM, incremental addressing, register top-5 ----------------
// grid (59, WAY, B_), 256 threads, 8 warps as 4M x 2N, warp tile 32x64.
__global__ __launch_bounds__(256, 2)
void gemm_kernel() {
    extern __shared__ char smem[];
    uint32_t sb = smem_u32(smem);

    int tid  = threadIdx.x;
    int lane = tid & 31;
    int wid  = tid >> 5;
    int wm   = wid >> 1;          // 0..3 (M quarter: 32 rows)
    int wn   = wid & 1;           // 0..1 (N half: 64 cols)

    int m0 = blockIdx.x * MT;
    int w  = blockIdx.y;
    int b  = blockIdx.z;

    const __half* Ab = g_qf + (size_t)b * QROWS * D_;
    const __half* Bb = g_sf + (size_t)(b * SROWS + w * SHW) * D_;

    // ---- prefetch state (incremental) ----
    int prow = tid >> 3;          // 0..31
    int pf4  = tid & 7;
    const __half* pA = Ab + (size_t)(m0 + prow) * D_ + pf4 * 8;
    const __half* pB = Bb + (size_t)prow * D_ + pf4 * 8;
    bool avalid[4];
#pragma unroll
    for (int i = 0; i < 4; i++) avalid[i] = (m0 + prow + i * 32) < QROWS;
    uint32_t dstA = (uint32_t)(prow * RSTR + pf4 * 16);
    int pkc = 0, pnt = 0, pcc = 0;
    uint32_t pstg = sb;

    auto prefetch = [&]() {
        if (pcc < TOTCH) {
#pragma unroll
            for (int i = 0; i < 4; i++)
                cp16(pstg + dstA + i * (32 * RSTR), pA + (size_t)i * (32 * D_), avalid[i]);
#pragma unroll
            for (int i = 0; i < 4; i++) {
                bool bv = (pnt * NTILE + prow + i * 32) < SHW;
                cp16(pstg + OFF_B + dstA + i * (32 * RSTR), pB + (size_t)i * (32 * D_), bv);
            }
            pstg += STAGE_BYTES;
            if (pstg == sb + NSTAGES * STAGE_BYTES) pstg = sb;
            if (++pkc == NCHUNK) {
                pkc = 0; pnt++;
                pA -= (NCHUNK - 1) * KC;                 // A repeats every nt
                pB += NTILE * D_ - (NCHUNK - 1) * KC;    // next 128 support rows
            } else {
                pA += KC; pB += KC;
            }
        }
        CP_COMMIT();
        pcc++;
    };

    // ---- per-thread ldsm offsets (constant; per-ks delta is +32) ----
    int arow = lane & 15;
    int ac16 = (lane >> 4) * 16;
    uint32_t offA[2];
#pragma unroll
    for (int mf = 0; mf < 2; mf++)
        offA[mf] = OFF_A + (uint32_t)((wm * 32 + mf * 16 + arow) * RSTR) + ac16;
    int bro  = lane & 7;
    int bc16 = ((lane >> 3) & 1) * 16;
    int nsel = lane >> 4;
    uint32_t offB[4];
#pragma unroll
    for (int nfp = 0; nfp < 4; nfp++)
        offB[nfp] = OFF_B + (uint32_t)((wn * 64 + (nfp * 2 + nsel) * 8 + bro) * RSTR) + bc16;

    float acc[2][8][4];
#pragma unroll
    for (int mf = 0; mf < 2; mf++)
#pragma unroll
        for (int nf = 0; nf < 8; nf++)
#pragma unroll
            for (int e = 0; e < 4; e++) acc[mf][nf][e] = 0.f;

    float t5[4][5];
#pragma unroll
    for (int r = 0; r < 4; r++)
#pragma unroll
        for (int k = 0; k < 5; k++) t5[r][k] = -1e30f;

    prefetch();
    prefetch();

    uint32_t cstg = sb;
    for (int nt = 0; nt < NTCOUNT; nt++) {
        for (int kc = 0; kc < NCHUNK; kc++) {
            CP_WAIT1();            // own chunk resident
            __syncthreads();       // all warps past previous use of this stage
            prefetch();            // refill stage (cc+2)%3 == (cc-1)%3

#pragma unroll
            for (int ks = 0; ks < 4; ks++) {
                uint32_t aF[2][4], bF[4][4];
#pragma unroll
                for (int mf = 0; mf < 2; mf++)
                    ldsm_x4(aF[mf], cstg + offA[mf] + ks * 32);
#pragma unroll
                for (int nfp = 0; nfp < 4; nfp++)
                    ldsm_x4(bF[nfp], cstg + offB[nfp] + ks * 32);
#pragma unroll
                for (int mf = 0; mf < 2; mf++)
#pragma unroll
                    for (int nfp = 0; nfp < 4; nfp++) {
                        mma_fp16(acc[mf][nfp*2],     aF[mf], &bF[nfp][0]);
                        mma_fp16(acc[mf][nfp*2 + 1], aF[mf], &bF[nfp][2]);
                    }
            }
            cstg += STAGE_BYTES;
            if (cstg == sb + NSTAGES * STAGE_BYTES) cstg = sb;
        }
        // ---- fold this N tile into per-thread running top-5 ----
        {
            bool lastnt = (nt == NTCOUNT - 1);
            int c2 = (lane & 3) * 2;
#pragma unroll
            for (int mf = 0; mf < 2; mf++)
#pragma unroll
                for (int e = 0; e < 2; e++) {
                    int tr = mf * 2 + e;
#pragma unroll
                    for (int nf = 0; nf < 8; nf++)
#pragma unroll
                        for (int j = 0; j < 2; j++) {
                            bool ok = true;
                            if (lastnt && wn == 1) {
                                int col = 384 + 64 + nf * 8 + c2 + j;
                                ok = col < SHW;
                            }
                            if (ok) top5_insert(t5[tr], acc[mf][nf][e*2 + j]);
                            acc[mf][nf][e*2 + j] = 0.f;
                        }
                }
        }
    }

    // ---- final merge: 8 holders x 5 candidates per row, via stage smem ----
    __syncthreads();
    float* cand = reinterpret_cast<float*>(smem); // [128][8][5] = 20KB
    int holder = wn * 4 + (lane & 3);
#pragma unroll
    for (int mf = 0; mf < 2; mf++)
#pragma unroll
        for (int e = 0; e < 2; e++) {
            int row = wm * 32 + mf * 16 + (lane >> 2) + e * 8;
#pragma unroll
            for (int k = 0; k < 5; k++)
                cand[(row * 8 + holder) * 5 + k] = t5[mf*2 + e][k];
        }
    __syncthreads();
    if (tid < 128) {
        const float* c = cand + tid * 40;
        float f[5];
#pragma unroll
        for (int k = 0; k < 5; k++) f[k] = -1e30f;
        for (int i = 0; i < 40; i++) top5_insert(f, c[i]);
        int gm = m0 + tid;
        if (gm < QROWS)
            g_rowsim[((size_t)(b * QROWS + gm)) * WAY + w] = f[0]+f[1]+f[2]+f[3]+f[4];
    }
}

// ---------------- reduce rowsim -> sim ----------------
__global__ void reduce_kernel() {
    int idx = blockIdx.x * blockDim.x + threadIdx.x;
    if (idx >= B_ * Q_ * WAY) return;
    int w  = idx % WAY;
    int bq = idx / WAY;
    int b  = bq / Q_;
    int q  = bq % Q_;
    const float* base = g_rowsim + ((size_t)b * QROWS + q * HW_) * WAY + w;
    float s = 0.f;
#pragma unroll 4
    for (int h = 0; h < HW_; h++) s += base[(size_t)h * WAY];
    g_sim[idx] = s * (1.0f / (HW_ * NK));
}

// ---------------- BN (two-pass variance) + dilated conv ----------------
__global__ void bnconv_kernel(const float* __restrict__ gamma,
                              const float* __restrict__ beta,
                              const float* __restrict__ convw,
                              float* __restrict__ out) {
    __shared__ float mu_s[B_*2*WAY], istd_s[B_*2*WAY];
    int t = threadIdx.x;
    if (t < B_*2*WAY) {
        int b = t / (2*WAY), c = t % (2*WAY);
        const float* src = (c < WAY) ? g_cos : g_sim;
        int ch = (c < WAY) ? c : c - WAY;
        float s = 0.f;
        for (int q = 0; q < Q_; q++) s += src[(b*Q_ + q) * WAY + ch];
        float m = s * (1.0f / Q_);
        float v = 0.f;
        for (int q = 0; q < Q_; q++) {
            float d = src[(b*Q_ + q) * WAY + ch] - m;
            v += d * d;
        }
        mu_s[t]   = m;
        istd_s[t] = rsqrtf(v * (1.0f / Q_) + 1e-5f);
    }
    __syncthreads();
    float w0 = convw[0], w1 = convw[1];
    for (int idx = t; idx < B_*Q_*WAY; idx += blockDim.x) {
        int j  = idx % WAY;
        int bq = idx / WAY;
        int b  = bq / Q_;
        float f0 = g_cos[bq * WAY + j];
        float f1 = g_sim[bq * WAY + j];
        float bn0 = (f0 - mu_s[b*2*WAY + j])       * istd_s[b*2*WAY + j]       * gamma[j]       + beta[j];
        float bn1 = (f1 - mu_s[b*2*WAY + j + WAY]) * istd_s[b*2*WAY + j + WAY] * gamma[j + WAY] + beta[j + WAY];
        out[idx] = w0 * bn0 + w1 * bn1;
    }
}

// ---------------- launch ----------------
extern "C" void kernel_launch(void* const* d_in, const int* in_sizes, int n_in,
                              void* d_out, int out_size) {
    const float* xq    = (const float*)d_in[0];
    const float* xs    = (const float*)d_in[1];
    const float* gamma = (const float*)d_in[2];
    const float* beta  = (const float*)d_in[3];
    const float* convw = (const float*)d_in[4];
    float* out = (float*)d_out;

    cudaFuncSetAttribute(gemm_kernel,
                         cudaFuncAttributeMaxDynamicSharedMemorySize, SMEM_TOTAL);

    int nrows = B_*QROWS + B_*SROWS;   // 40000 rows, 1 warp each
    prep_kernel<<<(nrows * 32 + 255) / 256, 256>>>(xq, xs);
    qmean_kernel<<<dim3(B_*Q_, 5), 128>>>();
    protopart_kernel<<<dim3(B_*WAY*SHOT, 5), 128>>>();
    gemm_kernel<<<dim3(MTILES, WAY, B_), 256, SMEM_TOTAL>>>();   // launch #4 -> ncu slot
    cos_kernel<<<B_*Q_*WAY, 32>>>();
    reduce_kernel<<<(B_*Q_*WAY + 255) / 256, 256>>>();
    bnconv_kernel<<<1, 256>>>(gamma, beta, convw, out);
}

// round 9
// speedup vs baseline: 7.0841x; 1.0254x over previous
#include <cuda_runtime.h>
#include <cuda_fp16.h>
#include <stdint.h>
#include <math.h>

// ---------------- problem constants ----------------
#define B_   4
#define Q_   75
#define WAY  5
#define SHOT 5
#define HW_  100
#define D_   640
#define NK   5
#define QROWS (Q_*HW_)        // 7500
#define SROWS (WAY*SHOT*HW_)  // 2500
#define SHW  (SHOT*HW_)       // 500

// ---------------- GEMM config ----------------
#define MT      128
#define NTILE   128
#define KC      64            // fp16 per k-chunk (128 bytes/row)
#define NCHUNK  (D_/KC)       // 10
#define NTCOUNT 4
#define TOTCH   (NTCOUNT*NCHUNK)  // 40
#define MTILES  59            // ceil(7500/128)

// smem: 3 stages of (A|B), padded-linear rows of 144 bytes (conflict-free ldmatrix)
#define RSTR    144
#define OFF_A   0
#define OFF_B   (128*RSTR)              // 18432
#define STAGE_BYTES (2*128*RSTR)        // 36864
#define NSTAGES 3
#define MB_OFF  (NSTAGES*STAGE_BYTES)   // 110592
#define SMEM_TOTAL (MB_OFF + 64)        // 110656 (x2 CTAs = 221312 <= 228KB)

// ---------------- scratch ----------------
__device__ __align__(16) __half g_qf[(size_t)B_*QROWS*D_];   // fp16 normalized
__device__ __align__(16) __half g_sf[(size_t)B_*SROWS*D_];
__device__ __align__(16) float g_qmean[B_*Q_*D_];
__device__ __align__(16) float g_ppart[B_*WAY*SHOT*D_];
__device__ __align__(16) float g_cos  [B_*Q_*WAY];
__device__ __align__(16) float g_sim  [B_*Q_*WAY];
__device__ __align__(16) float g_rowsim[(size_t)B_*QROWS*WAY];

// ---------------- asm helpers ----------------
__device__ __forceinline__ uint32_t smem_u32(const void* p) {
    uint32_t a;
    asm("{ .reg .u64 t; cvta.to.shared.u64 t, %1; cvt.u32.u64 %0, t; }" : "=r"(a) : "l"(p));
    return a;
}
__device__ __forceinline__ void cp16(uint32_t dst, const void* src, bool valid) {
    asm volatile("cp.async.cg.shared.global [%0], [%1], 16, %2;"
        :: "r"(dst), "l"(src), "r"(valid ? 16 : 0));
}
#define MB_INIT(addr, cnt) \
    asm volatile("mbarrier.init.shared.b64 [%0], %1;" :: "r"(addr), "r"(cnt) : "memory")
#define MB_ARRIVE(addr) \
    asm volatile("mbarrier.arrive.shared.b64 _, [%0];" :: "r"(addr) : "memory")
#define CP_MB_ARRIVE(addr) \
    asm volatile("cp.async.mbarrier.arrive.noinc.shared.b64 [%0];" :: "r"(addr) : "memory")
#define MB_WAIT(addr, par) do { \
    uint32_t _m = (addr); uint32_t _p = (par); uint32_t _d; \
    asm volatile("{\n\t.reg .pred p;\n\t" \
        "mbarrier.try_wait.parity.acquire.cta.shared::cta.b64 p, [%1], %2;\n\t" \
        "selp.b32 %0, 1, 0, p;\n\t}" : "=r"(_d) : "r"(_m), "r"(_p) : "memory"); \
    if (!_d) { \
        asm volatile("{\n\t.reg .pred P1;\n\t" \
            "WL_%=:\n\t" \
            "mbarrier.try_wait.parity.acquire.cta.shared::cta.b64 P1, [%0], %1, 0x989680;\n\t" \
            "@P1 bra.uni WD_%=;\n\t" \
            "bra.uni WL_%=;\n\t" \
            "WD_%=:\n\t}" :: "r"(_m), "r"(_p) : "memory"); \
    } \
} while(0)

__device__ __forceinline__ void ldsm_x4(uint32_t* r, uint32_t addr) {
    asm volatile("ldmatrix.sync.aligned.m8n8.x4.shared.b16 {%0,%1,%2,%3}, [%4];"
        : "=r"(r[0]), "=r"(r[1]), "=r"(r[2]), "=r"(r[3]) : "r"(addr));
}
__device__ __forceinline__ void mma_fp16(float* c, const uint32_t* a, const uint32_t* b) {
    asm volatile("mma.sync.aligned.m16n8k16.row.col.f32.f16.f16.f32 "
        "{%0,%1,%2,%3}, {%4,%5,%6,%7}, {%8,%9}, {%0,%1,%2,%3};"
        : "+f"(c[0]), "+f"(c[1]), "+f"(c[2]), "+f"(c[3])
        : "r"(a[0]), "r"(a[1]), "r"(a[2]), "r"(a[3]), "r"(b[0]), "r"(b[1]));
}

__device__ __forceinline__ void top5_insert(float* t, float v) {
    if (v > t[4]) {
        if (v > t[3]) { t[4] = t[3];
            if (v > t[2]) { t[3] = t[2];
                if (v > t[1]) { t[2] = t[1];
                    if (v > t[0]) { t[1] = t[0]; t[0] = v; } else t[1] = v;
                } else t[2] = v;
            } else t[3] = v;
        } else t[4] = v;
    }
}

// ---------------- prep: normalize -> fp16 copy ----------------
__global__ void prep_kernel(const float* __restrict__ xq, const float* __restrict__ xs) {
    int gw   = (blockIdx.x * blockDim.x + threadIdx.x) >> 5;
    int lane = threadIdx.x & 31;
    if (gw >= B_*QROWS + B_*SROWS) return;
    const float* src; __half* df;
    if (gw < B_*QROWS) {
        src = xq + (size_t)gw * D_;
        df = g_qf + (size_t)gw * D_;
    } else {
        int r = gw - B_*QROWS;
        src = xs + (size_t)r * D_;
        df = g_sf + (size_t)r * D_;
    }
    const float4* row4 = reinterpret_cast<const float4*>(src);
    float s = 0.f;
    float4 v[5];
#pragma unroll
    for (int i = 0; i < 5; i++) {
        v[i] = row4[lane + i * 32];
        s += v[i].x*v[i].x + v[i].y*v[i].y + v[i].z*v[i].z + v[i].w*v[i].w;
    }
#pragma unroll
    for (int o = 16; o; o >>= 1) s += __shfl_xor_sync(0xffffffffu, s, o);
    float inv = rsqrtf(s);
#pragma unroll
    for (int i = 0; i < 5; i++) {
        int e = (lane + i * 32) * 4;
        __half2 h0 = __floats2half2_rn(v[i].x*inv, v[i].y*inv);
        __half2 h1 = __floats2half2_rn(v[i].z*inv, v[i].w*inv);
        *reinterpret_cast<__half2*>(df + e)     = h0;
        *reinterpret_cast<__half2*>(df + e + 2) = h1;
    }
}

// ---------------- qmean from fp16 normalized ----------------
__global__ void qmean_kernel() {
    int bq = blockIdx.x;
    int d  = blockIdx.y * 128 + threadIdx.x;
    const __half* base = g_qf + (size_t)bq * HW_ * D_ + d;
    float s = 0.f;
#pragma unroll 4
    for (int h = 0; h < HW_; h++) s += __half2float(base[(size_t)h * D_]);
    g_qmean[(size_t)bq * D_ + d] = s * (1.0f / HW_);
}

// ---------------- proto partials from fp16 normalized ----------------
__global__ void protopart_kernel() {
    int bws = blockIdx.x;
    int d   = blockIdx.y * 128 + threadIdx.x;
    const __half* base = g_sf + (size_t)bws * HW_ * D_ + d;
    float s = 0.f;
#pragma unroll 4
    for (int h = 0; h < HW_; h++) s += __half2float(base[(size_t)h * D_]);
    g_ppart[(size_t)bws * D_ + d] = s;
}

// ---------------- cos logits ----------------
__global__ void cos_kernel() {
    int blk = blockIdx.x;
    int w  = blk % WAY;
    int bq = blk / WAY;
    int b  = bq / Q_;
    const float4* qm = reinterpret_cast<const float4*>(g_qmean + (size_t)bq * D_);
    const float4* pp = reinterpret_cast<const float4*>(g_ppart + (size_t)(b*WAY + w) * SHOT * D_);
    int lane = threadIdx.x;
    float s = 0.f;
#pragma unroll
    for (int i = 0; i < 5; i++) {
        int idx = lane + i * 32;
        float4 a = qm[idx];
        float4 p = make_float4(0.f, 0.f, 0.f, 0.f);
#pragma unroll
        for (int sh = 0; sh < SHOT; sh++) {
            float4 c = pp[(size_t)sh * (D_/4) + idx];
            p.x += c.x; p.y += c.y; p.z += c.z; p.w += c.w;
        }
        s += a.x*p.x + a.y*p.y + a.z*p.z + a.w*p.w;
    }
#pragma unroll
    for (int o = 16; o; o >>= 1) s += __shfl_xor_sync(0xffffffffu, s, o);
    if (lane == 0) g_cos[blk] = s * (1.0f / SHW);
}

// ---------------- fp16 MMA GEMM, mbarrier async pipeline, register top-5 ----------------
// grid (59, WAY, B_), 256 threads, 8 warps as 4M x 2N, warp tile 32x64.
// No __syncthreads in the mainloop: per-stage full/empty mbarriers decouple warps.
__global__ __launch_bounds__(256, 2)
void gemm_kernel() {
    extern __shared__ char smem[];
    uint32_t sb = smem_u32(smem);
    const uint32_t mbF = sb + MB_OFF;        // full[0..2], 8B each
    const uint32_t mbE = mbF + 24;           // empty[0..2]

    int tid  = threadIdx.x;
    int lane = tid & 31;
    int wid  = tid >> 5;
    int wm   = wid >> 1;          // 0..3 (M quarter: 32 rows)
    int wn   = wid & 1;           // 0..1 (N half: 64 cols)

    int m0 = blockIdx.x * MT;
    int w  = blockIdx.y;
    int b  = blockIdx.z;

    const __half* Ab = g_qf + (size_t)b * QROWS * D_;
    const __half* Bb = g_sf + (size_t)(b * SROWS + w * SHW) * D_;

    if (tid == 0) {
        MB_INIT(mbF + 0, 256); MB_INIT(mbF + 8, 256); MB_INIT(mbF + 16, 256);
        MB_INIT(mbE + 0, 8);   MB_INIT(mbE + 8, 8);   MB_INIT(mbE + 16, 8);
    }
    __syncthreads();

    // ---- producer state (incremental) ----
    int prow = tid >> 3;          // 0..31
    int pf4  = tid & 7;
    const __half* pA = Ab + (size_t)(m0 + prow) * D_ + pf4 * 8;
    const __half* pB = Bb + (size_t)prow * D_ + pf4 * 8;
    bool avalid[4];
#pragma unroll
    for (int i = 0; i < 4; i++) avalid[i] = (m0 + prow + i * 32) < QROWS;
    uint32_t dstA = (uint32_t)(prow * RSTR + pf4 * 16);
    int pkc = 0, pnt = 0, pcc = 0, pidx = 0;
    uint32_t pstg = sb;

    auto issue_chunk = [&]() {
#pragma unroll
        for (int i = 0; i < 4; i++)
            cp16(pstg + dstA + i * (32 * RSTR), pA + (size_t)i * (32 * D_), avalid[i]);
#pragma unroll
        for (int i = 0; i < 4; i++) {
            bool bv = (pnt * NTILE + prow + i * 32) < SHW;
            cp16(pstg + OFF_B + dstA + i * (32 * RSTR), pB + (size_t)i * (32 * D_), bv);
        }
        CP_MB_ARRIVE(mbF + 8 * pidx);
        pstg += STAGE_BYTES; if (++pidx == NSTAGES) { pidx = 0; pstg = sb; }
        if (++pkc == NCHUNK) {
            pkc = 0; pnt++;
            pA -= (NCHUNK - 1) * KC;                 // A repeats every nt
            pB += NTILE * D_ - (NCHUNK - 1) * KC;    // next 128 support rows
        } else {
            pA += KC; pB += KC;
        }
        pcc++;
    };

    // ---- per-thread ldsm offsets (constant; per-ks delta is +32) ----
    int arow = lane & 15;
    int ac16 = (lane >> 4) * 16;
    uint32_t offA[2];
#pragma unroll
    for (int mf = 0; mf < 2; mf++)
        offA[mf] = OFF_A + (uint32_t)((wm * 32 + mf * 16 + arow) * RSTR) + ac16;
    int bro  = lane & 7;
    int bc16 = ((lane >> 3) & 1) * 16;
    int nsel = lane >> 4;
    uint32_t offB[4];
#pragma unroll
    for (int nfp = 0; nfp < 4; nfp++)
        offB[nfp] = OFF_B + (uint32_t)((wn * 64 + (nfp * 2 + nsel) * 8 + bro) * RSTR) + bc16;

    float acc[2][8][4];
#pragma unroll
    for (int mf = 0; mf < 2; mf++)
#pragma unroll
        for (int nf = 0; nf < 8; nf++)
#pragma unroll
            for (int e = 0; e < 4; e++) acc[mf][nf][e] = 0.f;

    float t5[4][5];
#pragma unroll
    for (int r = 0; r < 4; r++)
#pragma unroll
        for (int k = 0; k < 5; k++) t5[r][k] = -1e30f;

    // bootstrap: chunks 0 and 1 (no empty wait needed; stages fresh)
    issue_chunk();
    issue_chunk();

    uint32_t fpar = 0, epar = 0;   // per-stage parity bitmasks
    int scur = 0;
    uint32_t cstg = sb;

    for (int nt = 0; nt < NTCOUNT; nt++) {
        for (int kc = 0; kc < NCHUNK; kc++) {
            // ---- producer: refill one stage ahead (chunk cc+2) ----
            if (pcc < TOTCH) {
                if (pcc >= NSTAGES) {
                    MB_WAIT(mbE + 8 * pidx, (epar >> pidx) & 1u);
                    epar ^= (1u << pidx);
                }
                issue_chunk();
            }
            // ---- consumer: wait data, compute ----
            MB_WAIT(mbF + 8 * scur, (fpar >> scur) & 1u);
            fpar ^= (1u << scur);

#pragma unroll
            for (int ks = 0; ks < 4; ks++) {
                uint32_t aF[2][4], bF[4][4];
#pragma unroll
                for (int mf = 0; mf < 2; mf++)
                    ldsm_x4(aF[mf], cstg + offA[mf] + ks * 32);
#pragma unroll
                for (int nfp = 0; nfp < 4; nfp++)
                    ldsm_x4(bF[nfp], cstg + offB[nfp] + ks * 32);
#pragma unroll
                for (int mf = 0; mf < 2; mf++)
#pragma unroll
                    for (int nfp = 0; nfp < 4; nfp++) {
                        mma_fp16(acc[mf][nfp*2],     aF[mf], &bF[nfp][0]);
                        mma_fp16(acc[mf][nfp*2 + 1], aF[mf], &bF[nfp][2]);
                    }
            }
            __syncwarp();
            if (lane == 0) MB_ARRIVE(mbE + 8 * scur);   // stage free for refill

            cstg += STAGE_BYTES; if (++scur == NSTAGES) { scur = 0; cstg = sb; }

            if (kc == NCHUNK - 1) {
                // ---- fold this N tile into per-thread running top-5 ----
                bool lastnt = (nt == NTCOUNT - 1);
                int c2 = (lane & 3) * 2;
#pragma unroll
                for (int mf = 0; mf < 2; mf++)
#pragma unroll
                    for (int e = 0; e < 2; e++) {
                        int tr = mf * 2 + e;
#pragma unroll
                        for (int nf = 0; nf < 8; nf++)
#pragma unroll
                            for (int j = 0; j < 2; j++) {
                                bool ok = true;
                                if (lastnt && wn == 1) {
                                    int col = 384 + 64 + nf * 8 + c2 + j;
                                    ok = col < SHW;
                                }
                                if (ok) top5_insert(t5[tr], acc[mf][nf][e*2 + j]);
                                acc[mf][nf][e*2 + j] = 0.f;
                            }
                    }
            }
        }
    }

    // ---- final merge: 8 holders x 5 candidates per row, via stage smem ----
    __syncthreads();
    float* cand = reinterpret_cast<float*>(smem); // [128][8][5] = 20KB
    int holder = wn * 4 + (lane & 3);
#pragma unroll
    for (int mf = 0; mf < 2; mf++)
#pragma unroll
        for (int e = 0; e < 2; e++) {
            int row = wm * 32 + mf * 16 + (lane >> 2) + e * 8;
#pragma unroll
            for (int k = 0; k < 5; k++)
                cand[(row * 8 + holder) * 5 + k] = t5[mf*2 + e][k];
        }
    __syncthreads();
    if (tid < 128) {
        const float* c = cand + tid * 40;
        float f[5];
#pragma unroll
        for (int k = 0; k < 5; k++) f[k] = -1e30f;
        for (int i = 0; i < 40; i++) top5_insert(f, c[i]);
        int gm = m0 + tid;
        if (gm < QROWS)
            g_rowsim[((size_t)(b * QROWS + gm)) * WAY + w] = f[0]+f[1]+f[2]+f[3]+f[4];
    }
}

// ---------------- reduce rowsim -> sim ----------------
__global__ void reduce_kernel() {
    int idx = blockIdx.x * blockDim.x + threadIdx.x;
    if (idx >= B_ * Q_ * WAY) return;
    int w  = idx % WAY;
    int bq = idx / WAY;
    int b  = bq / Q_;
    int q  = bq % Q_;
    const float* base = g_rowsim + ((size_t)b * QROWS + q * HW_) * WAY + w;
    float s = 0.f;
#pragma unroll 4
    for (int h = 0; h < HW_; h++) s += base[(size_t)h * WAY];
    g_sim[idx] = s * (1.0f / (HW_ * NK));
}

// ---------------- BN (two-pass variance) + dilated conv ----------------
__global__ void bnconv_kernel(const float* __restrict__ gamma,
                              const float* __restrict__ beta,
                              const float* __restrict__ convw,
                              float* __restrict__ out) {
    __shared__ float mu_s[B_*2*WAY], istd_s[B_*2*WAY];
    int t = threadIdx.x;
    if (t < B_*2*WAY) {
        int b = t / (2*WAY), c = t % (2*WAY);
        const float* src = (c < WAY) ? g_cos : g_sim;
        int ch = (c < WAY) ? c : c - WAY;
        float s = 0.f;
        for (int q = 0; q < Q_; q++) s += src[(b*Q_ + q) * WAY + ch];
        float m = s * (1.0f / Q_);
        float v = 0.f;
        for (int q = 0; q < Q_; q++) {
            float d = src[(b*Q_ + q) * WAY + ch] - m;
            v += d * d;
        }
        mu_s[t]   = m;
        istd_s[t] = rsqrtf(v * (1.0f / Q_) + 1e-5f);
    }
    __syncthreads();
    float w0 = convw[0], w1 = convw[1];
    for (int idx = t; idx < B_*Q_*WAY; idx += blockDim.x) {
        int j  = idx % WAY;
        int bq = idx / WAY;
        int b  = bq / Q_;
        float f0 = g_cos[bq * WAY + j];
        float f1 = g_sim[bq * WAY + j];
        float bn0 = (f0 - mu_s[b*2*WAY + j])       * istd_s[b*2*WAY + j]       * gamma[j]       + beta[j];
        float bn1 = (f1 - mu_s[b*2*WAY + j + WAY]) * istd_s[b*2*WAY + j + WAY] * gamma[j + WAY] + beta[j + WAY];
        out[idx] = w0 * bn0 + w1 * bn1;
    }
}

// ---------------- launch ----------------
extern "C" void kernel_launch(void* const* d_in, const int* in_sizes, int n_in,
                              void* d_out, int out_size) {
    const float* xq    = (const float*)d_in[0];
    const float* xs    = (const float*)d_in[1];
    const float* gamma = (const float*)d_in[2];
    const float* beta  = (const float*)d_in[3];
    const float* convw = (const float*)d_in[4];
    float* out = (float*)d_out;

    cudaFuncSetAttribute(gemm_kernel,
                         cudaFuncAttributeMaxDynamicSharedMemorySize, SMEM_TOTAL);

    int nrows = B_*QROWS + B_*SROWS;   // 40000 rows, 1 warp each
    prep_kernel<<<(nrows * 32 + 255) / 256, 256>>>(xq, xs);
    qmean_kernel<<<dim3(B_*Q_, 5), 128>>>();
    protopart_kernel<<<dim3(B_*WAY*SHOT, 5), 128>>>();
    gemm_kernel<<<dim3(MTILES, WAY, B_), 256, SMEM_TOTAL>>>();   // launch #4 -> ncu slot
    cos_kernel<<<B_*Q_*WAY, 32>>>();
    reduce_kernel<<<(B_*Q_*WAY + 255) / 256, 256>>>();
    bnconv_kernel<<<1, 256>>>(gamma, beta, convw, out);
}